// round 13
// baseline (speedup 1.0000x reference)
#include <cuda_runtime.h>
#include <cuda_bf16.h>
#include <math.h>

// ---------------- problem constants ----------------
#define NB   4
#define NT   500
#define NF   65
#define NC   128
#define NH   8
#define NBH  32
#define DQK  260        // F*E_DIM
#define DV   1040       // F*V_DIM
#define FC   8320       // F*C
#define EPSV 1e-5f
#define OUT_ELEMS 16640000
#define KBUF_ELEMS 74880     // 32*9*260
#define VBUF_ELEMS 299520    // 32*9*1040

typedef unsigned long long u64;
typedef unsigned int u32;
typedef unsigned short u16;

// ---------------- scratch (__device__ globals; no runtime alloc) ------------
__device__ float d_Qr [(size_t)NBH * DQK * NT];
__device__ float d_KrP[16 + (size_t)NBH * DQK * NT];
__device__ float d_VrP[16 + (size_t)NBH * DV  * NT];
#define d_Kr (d_KrP + 16)
#define d_Vr (d_VrP + 16)
__device__ float d_Z [(size_t)NB * NF * NC * NT]; // [b][f][cc][t]  cc = h*16+dv
__device__ float d_Y [(size_t)NB * NC * NF * NT]; // [b][o][f][t]
__device__ float d_muq[NBH * NT], d_rsq[NBH * NT];
__device__ float d_muk[NBH * NT], d_rsk[NBH * NT];
__device__ float d_muv[NBH * NT], d_rsv[NBH * NT];
__device__ float d_mup[NB * NT],  d_rsp[NB * NT];
__device__ float d_part_s [12 * NBH * NT], d_part_ss[12 * NBH * NT];
__device__ float d_ps [NF * NB * NT], d_pss[NF * NB * NT];
#define CFSTR (NBH * NT)
__device__ float d_cf [24 * CFSTR];
__device__ float d_dummy[1024];

// Pre-baked per-lane B fragment arrays: [nt][kk(24)][lane(32)] -> u64 (b0,b1)
// virtual K sections: kk 0..7 = Bh, 8..15 = Bl, 16..23 = Bh
__device__ u64 g_Bkv[20 * 24 * 32];   // 160 outputs (K 32 + V 128)
__device__ u64 g_Bq [4  * 24 * 32];   // 32 outputs
__device__ u64 g_Bp [16 * 24 * 32];   // 128 outputs

// ---------------- warp mma helper -------------------------------------------
__device__ __forceinline__ void mma16816(float* c, u32 a0, u32 a1, u32 a2, u32 a3,
                                         u32 b0, u32 b1) {
    asm volatile(
        "mma.sync.aligned.m16n8k16.row.col.f32.bf16.bf16.f32 "
        "{%0,%1,%2,%3}, {%4,%5,%6,%7}, {%8,%9}, {%0,%1,%2,%3};"
        : "+f"(c[0]), "+f"(c[1]), "+f"(c[2]), "+f"(c[3])
        : "r"(a0), "r"(a1), "r"(a2), "r"(a3), "r"(b0), "r"(b1));
}

// A fragment store: value a at (local t-row r 0..127, channel c 0..127)
// layout [mi(8)][kf(16)][lane(32)] x 16B ; kf 0..7 = Ah, 8..15 = Al
__device__ __forceinline__ void storeAfrag(char* As, int r, int c, float a) {
    __nv_bfloat16 bh = __float2bfloat16(a);
    __nv_bfloat16 bl = __float2bfloat16(a - __bfloat162float(bh));
    int mi = r >> 4, rl = r & 15;
    int kl = c & 15;
    int lane = (rl & 7) * 4 + ((kl & 7) >> 1);
    int sub = ((rl >> 3) + 2 * (kl >> 3)) * 4 + (kl & 1) * 2;
    int bh_off = (((mi * 16 + (c >> 4)) * 32 + lane) << 4) + sub;
    int bl_off = (((mi * 16 + 8 + (c >> 4)) * 32 + lane) << 4) + sub;
    *(__nv_bfloat16*)(As + bh_off) = bh;
    *(__nv_bfloat16*)(As + bl_off) = bl;
}

// ---------------- warmup no-op ----------------------------------------------
__global__ void k_warm() {
    int i = blockIdx.x * 128 + threadIdx.x;
    if (i < 1024) d_dummy[i] = 0.f;
}

// ======= k_prep: bake B fragment arrays =====================================
__global__ void k_prep(const float* __restrict__ Wq, const float* __restrict__ Wk,
                       const float* __restrict__ Wv, const float* __restrict__ Wp)
{
    int idx = blockIdx.x * 256 + threadIdx.x;
    if (idx >= 40960) return;
    float w; __nv_bfloat16* img; int o, c;
    if (idx < 20480) {
        o = idx >> 7; c = idx & 127;
        w = (o < 32) ? Wk[o * 128 + c] : Wv[(o - 32) * 128 + c];
        img = (__nv_bfloat16*)g_Bkv;
    } else if (idx < 24576) {
        int i = idx - 20480; o = i >> 7; c = i & 127;
        w = Wq[o * 128 + c];
        img = (__nv_bfloat16*)g_Bq;
    } else {
        int i = idx - 24576; o = i >> 7; c = i & 127;
        w = Wp[o * 128 + c];
        img = (__nv_bfloat16*)g_Bp;
    }
    __nv_bfloat16 bh = __float2bfloat16(w);
    __nv_bfloat16 bl = __float2bfloat16(w - __bfloat162float(bh));
    int nt = o >> 3, n = o & 7;
    int kl = c & 15;
    int lane = n * 4 + ((kl & 7) >> 1);
    int sub = (kl >> 3) * 2 + (kl & 1);
#pragma unroll
    for (int s = 0; s < 3; s++) {
        int kk = s * 8 + (c >> 4);
        __nv_bfloat16 val = (s == 1) ? bl : bh;
        img[((nt * 24 + kk) * 32 + lane) * 4 + sub] = val;
    }
}

// ======= kernel 1a: K+V projection via mma.sync (N=160) =====================
#define GEMM_SMEM 65536
__global__ __launch_bounds__(256)
void k_kv_mma(const float* __restrict__ mc,
              const float* __restrict__ bk, const float* __restrict__ ak,
              const float* __restrict__ bv, const float* __restrict__ av)
{
    extern __shared__ char sA[];
    const int tid = threadIdx.x, wid = tid >> 5, lane = tid & 31;
    const int f = blockIdx.y, b = blockIdx.z;
    const int t0 = blockIdx.x * 128;

    for (int i = tid; i < 128 * 32; i += 256) {
        int c = i >> 5, tq = i & 31;
        int t = t0 + tq * 4;
        float4 v = make_float4(0.f, 0.f, 0.f, 0.f);
        if (t < NT) v = *(const float4*)(mc + ((size_t)(b * NC + c) * NF + f) * NT + t);
        storeAfrag(sA, tq * 4 + 0, c, v.x);
        storeAfrag(sA, tq * 4 + 1, c, v.y);
        storeAfrag(sA, tq * 4 + 2, c, v.z);
        storeAfrag(sA, tq * 4 + 3, c, v.w);
    }
    __syncthreads();

    float acc[20][4];
#pragma unroll
    for (int nt = 0; nt < 20; nt++)
#pragma unroll
        for (int r = 0; r < 4; r++) acc[nt][r] = 0.f;

    const int mi = wid;
    const uint4* Aptr = (const uint4*)sA + (mi * 16 * 32 + lane);
#pragma unroll 1
    for (int kk = 0; kk < 24; kk++) {
        int af = (kk < 8) ? kk : kk - 8;
        uint4 A = Aptr[af * 32];
        const u64* bp = g_Bkv + kk * 32 + lane;
#pragma unroll
        for (int nt = 0; nt < 20; nt++) {
            u64 bb = bp[nt * 768];
            mma16816(acc[nt], A.x, A.y, A.z, A.w, (u32)bb, (u32)(bb >> 32));
        }
    }

    const int g = lane >> 2, tg = lane & 3;
    const float akv = ak[0], avv = av[0];
#pragma unroll
    for (int nt = 0; nt < 20; nt++) {
#pragma unroll
        for (int r = 0; r < 4; r++) {
            int e = r & 1, hr = r >> 1;
            int o = nt * 8 + tg * 2 + e;
            int t = t0 + mi * 16 + g + 8 * hr;
            if (t >= NT) continue;
            float v = acc[nt][r];
            if (o < 32) {
                v += bk[o]; v = v >= 0.f ? v : akv * v;
                d_Kr[((size_t)(b * 8 + (o >> 2)) * DQK + f * 4 + (o & 3)) * NT + t] = v;
            } else {
                int vv = o - 32;
                v += bv[vv]; v = v >= 0.f ? v : avv * v;
                d_Vr[((size_t)(b * 8 + (vv >> 4)) * DV + f * 16 + (vv & 15)) * NT + t] = v;
            }
        }
    }
}

// ======= kernel 1b: Q projection via mma.sync (N=32) ========================
__global__ __launch_bounds__(256)
void k_q_mma(const float* __restrict__ x,
             const float* __restrict__ bq, const float* __restrict__ aq)
{
    extern __shared__ char sA[];
    const int tid = threadIdx.x, wid = tid >> 5, lane = tid & 31;
    const int f = blockIdx.y, b = blockIdx.z;
    const int t0 = blockIdx.x * 128;

    for (int i = tid; i < 128 * 32; i += 256) {
        int c = i >> 5, tq = i & 31;
        int t = t0 + tq * 4;
        float4 v = make_float4(0.f, 0.f, 0.f, 0.f);
        if (t < NT) v = *(const float4*)(x + ((size_t)(b * NC + c) * NF + f) * NT + t);
        storeAfrag(sA, tq * 4 + 0, c, v.x);
        storeAfrag(sA, tq * 4 + 1, c, v.y);
        storeAfrag(sA, tq * 4 + 2, c, v.z);
        storeAfrag(sA, tq * 4 + 3, c, v.w);
    }
    __syncthreads();

    float acc[4][4];
#pragma unroll
    for (int nt = 0; nt < 4; nt++)
#pragma unroll
        for (int r = 0; r < 4; r++) acc[nt][r] = 0.f;

    const int mi = wid;
    const uint4* Aptr = (const uint4*)sA + (mi * 16 * 32 + lane);
#pragma unroll 1
    for (int kk = 0; kk < 24; kk++) {
        int af = (kk < 8) ? kk : kk - 8;
        uint4 A = Aptr[af * 32];
        const u64* bp = g_Bq + kk * 32 + lane;
#pragma unroll
        for (int nt = 0; nt < 4; nt++) {
            u64 bb = bp[nt * 768];
            mma16816(acc[nt], A.x, A.y, A.z, A.w, (u32)bb, (u32)(bb >> 32));
        }
    }

    const int g = lane >> 2, tg = lane & 3;
    const float aqv = aq[0];
#pragma unroll
    for (int nt = 0; nt < 4; nt++) {
#pragma unroll
        for (int r = 0; r < 4; r++) {
            int e = r & 1, hr = r >> 1;
            int o = nt * 8 + tg * 2 + e;
            int t = t0 + mi * 16 + g + 8 * hr;
            if (t >= NT) continue;
            float v = acc[nt][r] + bq[o];
            v = v >= 0.f ? v : aqv * v;
            d_Qr[((size_t)(b * 8 + (o >> 2)) * DQK + f * 4 + (o & 3)) * NT + t] = v;
        }
    }
}

// ======= kernel 4: P projection via mma.sync (N=128) + fused LN-P partials ==
__global__ __launch_bounds__(256)
void k_p_mma(const float* __restrict__ bp_, const float* __restrict__ ap)
{
    extern __shared__ char sA[];
    const int tid = threadIdx.x, wid = tid >> 5, lane = tid & 31;
    const int f = blockIdx.y, b = blockIdx.z;
    const int t0 = blockIdx.x * 128;

    for (int i = tid; i < 128 * 32; i += 256) {
        int c = i >> 5, tq = i & 31;
        int t = t0 + tq * 4;
        float4 v = make_float4(0.f, 0.f, 0.f, 0.f);
        if (t < NT) v = *(const float4*)(d_Z + ((size_t)(b * NF + f) * NC + c) * NT + t);
        storeAfrag(sA, tq * 4 + 0, c, v.x);
        storeAfrag(sA, tq * 4 + 1, c, v.y);
        storeAfrag(sA, tq * 4 + 2, c, v.z);
        storeAfrag(sA, tq * 4 + 3, c, v.w);
    }
    __syncthreads();

    float acc[16][4];
#pragma unroll
    for (int nt = 0; nt < 16; nt++)
#pragma unroll
        for (int r = 0; r < 4; r++) acc[nt][r] = 0.f;

    const int mi = wid;
    const uint4* Aptr = (const uint4*)sA + (mi * 16 * 32 + lane);
#pragma unroll 1
    for (int kk = 0; kk < 24; kk++) {
        int af = (kk < 8) ? kk : kk - 8;
        uint4 A = Aptr[af * 32];
        const u64* bp = g_Bp + kk * 32 + lane;
#pragma unroll
        for (int nt = 0; nt < 16; nt++) {
            u64 bb = bp[nt * 768];
            mma16816(acc[nt], A.x, A.y, A.z, A.w, (u32)bb, (u32)(bb >> 32));
        }
    }

    const int g = lane >> 2, tg = lane & 3;
    const float apv = ap[0];
    float s_[2] = {0.f, 0.f}, ss_[2] = {0.f, 0.f};
#pragma unroll
    for (int nt = 0; nt < 16; nt++) {
#pragma unroll
        for (int r = 0; r < 4; r++) {
            int e = r & 1, hr = r >> 1;
            int o = nt * 8 + tg * 2 + e;
            int t = t0 + mi * 16 + g + 8 * hr;
            float v = acc[nt][r] + bp_[o];
            v = v >= 0.f ? v : apv * v;
            if (t < NT) d_Y[((size_t)(b * NC + o) * NF + f) * NT + t] = v;
            s_[hr] += v;
            ss_[hr] = fmaf(v, v, ss_[hr]);
        }
    }
    // reduce over the 4 tg lanes (same t)
#pragma unroll
    for (int hr = 0; hr < 2; hr++) {
        s_[hr]  += __shfl_xor_sync(0xffffffffu, s_[hr], 1);
        s_[hr]  += __shfl_xor_sync(0xffffffffu, s_[hr], 2);
        ss_[hr] += __shfl_xor_sync(0xffffffffu, ss_[hr], 1);
        ss_[hr] += __shfl_xor_sync(0xffffffffu, ss_[hr], 2);
        int t = t0 + mi * 16 + g + 8 * hr;
        if (tg == 0 && t < NT) {
            d_ps [(f * NB + b) * NT + t] = s_[hr];
            d_pss[(f * NB + b) * NT + t] = ss_[hr];
        }
    }
}

// ============ kernel 2: merged Q/K/V LN stats, split-d partials =============
__global__ void k_stats_part() {
    int t = blockIdx.x * 128 + threadIdx.x;
    if (t >= NT) return;
    int bh = blockIdx.y, s = blockIdx.z;
    const float* p;
    if (s < 2)      p = d_Qr + ((size_t)bh * DQK + s * 130) * NT + t;
    else if (s < 4) p = d_Kr + ((size_t)bh * DQK + (s - 2) * 130) * NT + t;
    else            p = d_Vr + ((size_t)bh * DV  + (s - 4) * 130) * NT + t;
    float sum = 0.f, ss = 0.f;
#pragma unroll 10
    for (int i = 0; i < 130; i++) { float v = p[(size_t)i * NT]; sum += v; ss += v * v; }
    int o = (s * NBH + bh) * NT + t;
    d_part_s[o] = sum;
    d_part_ss[o] = ss;
}
__global__ void k_stats_comb() {
    int t = blockIdx.x * 128 + threadIdx.x;
    if (t >= NT) return;
    int bh = blockIdx.y;
    float s, ss, m, var;
    s = d_part_s[(0 * NBH + bh) * NT + t] + d_part_s[(1 * NBH + bh) * NT + t];
    ss = d_part_ss[(0 * NBH + bh) * NT + t] + d_part_ss[(1 * NBH + bh) * NT + t];
    m = s * (1.f / DQK); var = ss * (1.f / DQK) - m * m;
    d_muq[bh * NT + t] = m; d_rsq[bh * NT + t] = rsqrtf(var + EPSV);
    s = d_part_s[(2 * NBH + bh) * NT + t] + d_part_s[(3 * NBH + bh) * NT + t];
    ss = d_part_ss[(2 * NBH + bh) * NT + t] + d_part_ss[(3 * NBH + bh) * NT + t];
    m = s * (1.f / DQK); var = ss * (1.f / DQK) - m * m;
    d_muk[bh * NT + t] = m; d_rsk[bh * NT + t] = rsqrtf(var + EPSV);
    s = 0.f; ss = 0.f;
#pragma unroll
    for (int sl = 4; sl < 12; sl++) {
        s += d_part_s[(sl * NBH + bh) * NT + t];
        ss += d_part_ss[(sl * NBH + bh) * NT + t];
    }
    m = s * (1.f / DV); var = ss * (1.f / DV) - m * m;
    d_muv[bh * NT + t] = m; d_rsv[bh * NT + t] = rsqrtf(var + EPSV);
}

// ========== kernel 3a: scores + softmax -> coefficient vectors (SoA) ========
__global__ __launch_bounds__(128)
void k_score(const float* __restrict__ Kbuf,
             const float* __restrict__ gq, const float* __restrict__ beq,
             const float* __restrict__ gk, const float* __restrict__ bek)
{
    __shared__ float sp[32][4][4][12];

    const int tid = threadIdx.x;
    const int tl = tid & 3, dg = tid >> 2;
    const int bh = blockIdx.y;
    const int t0 = blockIdx.x * 16;
    const int t4 = t0 + 4 * tl;
    const int t4c = (t4 < NT) ? t4 : (NT - 4);

    const float* Qp = d_Qr + (size_t)bh * DQK * NT;
    const float* Kp = d_Kr + (size_t)bh * DQK * NT;

    {
        const float4 muq4 = *(const float4*)(d_muq + bh * NT + t4c);
        const float4 rsq4 = *(const float4*)(d_rsq + bh * NT + t4c);
        const float mu[4] = {muq4.x, muq4.y, muq4.z, muq4.w};
        const float rs[4] = {rsq4.x, rsq4.y, rsq4.z, rsq4.w};
        float s[4][10];
#pragma unroll
        for (int j = 0; j < 4; j++)
#pragma unroll
            for (int c = 0; c < 10; c++) s[j][c] = 0.f;
        float Qg[4] = {0.f, 0.f, 0.f, 0.f}, Qb[4] = {0.f, 0.f, 0.f, 0.f};

        int d0 = dg * 9, d1 = d0 + 9; if (d1 > DQK) d1 = DQK;
        for (int d = d0; d < d1; d++) {
            const float4 q4 = *(const float4*)(Qp + (size_t)d * NT + t4c);
            const float qv[4] = {q4.x, q4.y, q4.z, q4.w};
            const float gqd = gq[d], beqd = beq[d], gkd = gk[d], bekd = bek[d];
            float w[16];
            const float* kb = Kp + (size_t)d * NT + t4c - 12;
            *(float4*)&w[0]  = *(const float4*)(kb);
            *(float4*)&w[4]  = *(const float4*)(kb + 4);
            *(float4*)&w[8]  = *(const float4*)(kb + 8);
            *(float4*)&w[12] = *(const float4*)(kb + 12);
            float qg[4];
#pragma unroll
            for (int j = 0; j < 4; j++) {
                float qn = fmaf((qv[j] - mu[j]) * rs[j], gqd, beqd);
                qg[j] = qn * gkd;
                Qg[j] += qg[j];
                Qb[j] = fmaf(qn, bekd, Qb[j]);
            }
#pragma unroll
            for (int c = 0; c < 10; c++)
#pragma unroll
                for (int j = 0; j < 4; j++)
                    s[j][c] = fmaf(qg[j], w[3 + j + c], s[j][c]);
        }
#pragma unroll
        for (int j = 0; j < 4; j++) {
#pragma unroll
            for (int c = 0; c < 10; c++) sp[dg][tl][j][c] = s[j][c];
            sp[dg][tl][j][10] = Qg[j];
            sp[dg][tl][j][11] = Qb[j];
        }
    }
    __syncthreads();

    if (tid < 16) {
        const int tt = tid, jj = tt & 3, tln = tt >> 2;
        int t = t0 + tt;
        if (t >= NT) return;
        const int tc = t;
        float S[10], QG = 0.f, QB = 0.f;
#pragma unroll
        for (int c = 0; c < 10; c++) S[c] = 0.f;
#pragma unroll
        for (int g = 0; g < 32; g++) {
#pragma unroll
            for (int c = 0; c < 10; c++) S[c] += sp[g][tln][jj][c];
            QG += sp[g][tln][jj][10];
            QB += sp[g][tln][jj][11];
        }
        const int c0 = (tc < 9) ? (9 - tc) : 0;
#pragma unroll
        for (int c = 0; c < 10; c++) {
            int src = tc + c - 9;
            int sc = src < 0 ? 0 : src;
            float mk = d_muk[bh * NT + sc], rk = d_rsk[bh * NT + sc];
            S[c] = rk * (S[c] - mk * QG) + QB;
        }
        if (c0 > 0) {
            const float muq = d_muq[bh * NT + tc], rsq = d_rsq[bh * NT + tc];
            for (int c = 0; c < c0; c++) {
                const float* kb = Kbuf + ((size_t)bh * 9 + (tc + c)) * DQK;
                float acc = 0.f;
                for (int d = 0; d < DQK; d++) {
                    float qr = Qp[(size_t)d * NT + tc];
                    float qn = (qr - muq) * rsq * gq[d] + beq[d];
                    acc = fmaf(qn, kb[d], acc);
                }
                S[c] = acc;
            }
        }
        const float SCL = 0.0620173672946042252f;  // 1/sqrt(260)
        float mx = -1e30f;
#pragma unroll
        for (int c = 0; c < 10; c++) { S[c] *= SCL; mx = fmaxf(mx, S[c]); }
        float p[10], psum = 0.f;
#pragma unroll
        for (int c = 0; c < 10; c++) { p[c] = expf(S[c] - mx); psum += p[c]; }
        float inv = 1.f / psum;
        const int cfo = bh * NT + t;
        float boff = 0.f, P = 0.f;
#pragma unroll
        for (int c = 0; c < 10; c++) {
            p[c] *= inv;
            d_cf[c * CFSTR + cfo] = p[c];
            int src = tc + c - 9;
            float a = 0.f;
            if (src >= 0) {
                float mv_ = d_muv[bh * NT + src], rv_ = d_rsv[bh * NT + src];
                a = p[c] * rv_;
                boff -= a * mv_;
                P += p[c];
            }
            d_cf[(10 + c) * CFSTR + cfo] = a;
        }
        d_cf[20 * CFSTR + cfo] = boff;
        d_cf[21 * CFSTR + cfo] = P;
    }
}

// ========== kernel 3b: Vo FIR ===============================================
__global__ __launch_bounds__(256)
void k_vo(const float* __restrict__ Vbuf,
          const float* __restrict__ gv, const float* __restrict__ bev)
{
    const int tid = threadIdx.x;
    const int tl = tid & 31, dl = tid >> 5;
    const int bh = blockIdx.z;
    const int b = bh >> 3, h = bh & 7;
    const int t4 = blockIdx.x * 128 + 4 * tl;
    const bool vld = t4 < NT;
    const int t4c = vld ? t4 : (NT - 4);
    const int dbase = blockIdx.y * 80 + dl * 10;
    const int cfo = bh * NT + t4c;

    float a[4][10], boff[4], Pv[4];
#pragma unroll
    for (int c = 0; c < 10; c++) {
        float4 a4 = *(const float4*)(d_cf + (10 + c) * CFSTR + cfo);
        a[0][c] = a4.x; a[1][c] = a4.y; a[2][c] = a4.z; a[3][c] = a4.w;
    }
    {
        float4 b4 = *(const float4*)(d_cf + 20 * CFSTR + cfo);
        boff[0] = b4.x; boff[1] = b4.y; boff[2] = b4.z; boff[3] = b4.w;
        float4 p4 = *(const float4*)(d_cf + 21 * CFSTR + cfo);
        Pv[0] = p4.x; Pv[1] = p4.y; Pv[2] = p4.z; Pv[3] = p4.w;
    }
    const bool anybuf = (t4c < 9);
    const float* Vp = d_Vr + (size_t)bh * DV * NT;

#pragma unroll 2
    for (int i = 0; i < 10; i++) {
        const int d = dbase + i;
        float w[16];
        const float* vb = Vp + (size_t)d * NT + t4c - 12;
        *(float4*)&w[0]  = *(const float4*)(vb);
        *(float4*)&w[4]  = *(const float4*)(vb + 4);
        *(float4*)&w[8]  = *(const float4*)(vb + 8);
        *(float4*)&w[12] = *(const float4*)(vb + 12);
        float acc[4] = {boff[0], boff[1], boff[2], boff[3]};
#pragma unroll
        for (int c = 0; c < 10; c++)
#pragma unroll
            for (int j = 0; j < 4; j++)
                acc[j] = fmaf(a[j][c], w[3 + j + c], acc[j]);
        const float gvd = gv[d], bevd = bev[d];
        float vo[4];
#pragma unroll
        for (int j = 0; j < 4; j++) vo[j] = fmaf(gvd, acc[j], bevd * Pv[j]);
        if (anybuf) {
#pragma unroll
            for (int j = 0; j < 4; j++) {
                int tj = t4c + j;
                int cb = 9 - tj;
                for (int c = 0; c < cb; c++)
                    vo[j] = fmaf(d_cf[c * CFSTR + bh * NT + tj],
                                 Vbuf[((size_t)bh * 9 + (tj + c)) * DV + d], vo[j]);
            }
        }
        if (vld) {
            int f = d >> 4, dvv = d & 15;
            float4 o4 = make_float4(vo[0], vo[1], vo[2], vo[3]);
            *(float4*)(d_Z + (((size_t)b * NF + f) * NC + h * 16 + dvv) * NT + t4) = o4;
        }
    }
}

// ============ kernel 5: LN-P stats combine over 65 f-partials ===============
__global__ void k_statsP2() {
    int t = blockIdx.x * 128 + threadIdx.x;
    if (t >= NT) return;
    int b = blockIdx.y;
    float s = 0.f, ss = 0.f;
#pragma unroll 5
    for (int f = 0; f < NF; f++) {
        s += d_ps [(f * NB + b) * NT + t];
        ss += d_pss[(f * NB + b) * NT + t];
    }
    float m = s * (1.f / FC);
    float var = ss * (1.f / FC) - m * m;
    d_mup[b * NT + t] = m;
    d_rsp[b * NT + t] = rsqrtf(var + EPSV);
}

// ========== kernel 6: LN-P apply + residual + output (float4) ===============
__global__ void k_final(const float* __restrict__ x, const float* __restrict__ gp,
                        const float* __restrict__ bep, float* __restrict__ out)
{
    size_t idx4 = (size_t)blockIdx.x * 256 + threadIdx.x;
    if (idx4 >= (size_t)(OUT_ELEMS / 4)) return;
    size_t i = idx4 * 4;
    int t = (int)(i % NT);
    size_t r = i / NT;
    int f = (int)(r % NF); r /= NF;
    int o = (int)(r % NC);
    int b = (int)(r / NC);
    float4 y = *(const float4*)(d_Y + i);
    float4 xv = *(const float4*)(x + i);
    float4 m4 = *(const float4*)(d_mup + b * NT + t);
    float4 r4 = *(const float4*)(d_rsp + b * NT + t);
    int gi = f * NC + o;
    float g = gp[gi], be = bep[gi];
    float4 ov;
    ov.x = (y.x - m4.x) * r4.x * g + be + xv.x;
    ov.y = (y.y - m4.y) * r4.y * g + be + xv.y;
    ov.z = (y.z - m4.z) * r4.z * g + be + xv.z;
    ov.w = (y.w - m4.w) * r4.w * g + be + xv.w;
    *(float4*)(out + i) = ov;
}

// ================= kernel 7: K_buf_new / V_buf_new ==========================
__global__ void k_bufs(const float* __restrict__ gk, const float* __restrict__ bek,
                       const float* __restrict__ gv, const float* __restrict__ bev,
                       float* __restrict__ kout, float* __restrict__ vout)
{
    int idx = blockIdx.x * 256 + threadIdx.x;
    if (idx < KBUF_ELEMS) {
        int d = idx % DQK; int r = idx / DQK; int j = r % 9; int bh = r / 9;
        int t = 491 + j;
        float v = d_Kr[((size_t)bh * DQK + d) * NT + t];
        v = (v - d_muk[bh * NT + t]) * d_rsk[bh * NT + t] * gk[d] + bek[d];
        kout[idx] = v;
    } else {
        int i2 = idx - KBUF_ELEMS;
        if (i2 < VBUF_ELEMS) {
            int d = i2 % DV; int r = i2 / DV; int j = r % 9; int bh = r / 9;
            int t = 491 + j;
            float v = d_Vr[((size_t)bh * DV + d) * NT + t];
            v = (v - d_muv[bh * NT + t]) * d_rsv[bh * NT + t] * gv[d] + bev[d];
            vout[i2] = v;
        }
    }
}

// ================= launch ==================================================
extern "C" void kernel_launch(void* const* d_in, const int* in_sizes, int n_in,
                              void* d_out, int out_size)
{
    const float* x    = (const float*)d_in[0];
    const float* mc   = (const float*)d_in[1];
    const float* Kbuf = (const float*)d_in[2];
    const float* Vbuf = (const float*)d_in[3];
    const float* Wq   = (const float*)d_in[4];
    const float* bq   = (const float*)d_in[5];
    const float* aq   = (const float*)d_in[6];
    const float* gq   = (const float*)d_in[7];
    const float* beq  = (const float*)d_in[8];
    const float* Wk   = (const float*)d_in[9];
    const float* bk   = (const float*)d_in[10];
    const float* ak   = (const float*)d_in[11];
    const float* gk   = (const float*)d_in[12];
    const float* bek  = (const float*)d_in[13];
    const float* Wv   = (const float*)d_in[14];
    const float* bv   = (const float*)d_in[15];
    const float* av   = (const float*)d_in[16];
    const float* gv   = (const float*)d_in[17];
    const float* bev  = (const float*)d_in[18];
    const float* Wp   = (const float*)d_in[19];
    const float* bp   = (const float*)d_in[20];
    const float* ap   = (const float*)d_in[21];
    const float* gp   = (const float*)d_in[22];
    const float* bep  = (const float*)d_in[23];
    float* out = (float*)d_out;

    cudaFuncSetAttribute(k_kv_mma, cudaFuncAttributeMaxDynamicSharedMemorySize, GEMM_SMEM);
    cudaFuncSetAttribute(k_q_mma,  cudaFuncAttributeMaxDynamicSharedMemorySize, GEMM_SMEM);
    cudaFuncSetAttribute(k_p_mma,  cudaFuncAttributeMaxDynamicSharedMemorySize, GEMM_SMEM);

    // slots 0-2: warm + prep, so ncu's captured launch (index 3) = k_kv_mma
    k_warm<<<8, 128>>>();
    k_warm<<<8, 128>>>();
    k_prep<<<160, 256>>>(Wq, Wk, Wv, Wp);
    k_kv_mma<<<dim3(4, 65, 4), 256, GEMM_SMEM>>>(mc, bk, ak, bv, av);
    k_q_mma<<<dim3(4, 65, 4), 256, GEMM_SMEM>>>(x, bq, aq);
    k_stats_part<<<dim3(4, 32, 12), 128>>>();
    k_stats_comb<<<dim3(4, 32), 128>>>();
    k_score<<<dim3(32, 32), 128>>>(Kbuf, gq, beq, gk, bek);
    k_vo<<<dim3(4, 13, 32), 256>>>(Vbuf, gv, bev);
    k_p_mma<<<dim3(4, 65, 4), 256, GEMM_SMEM>>>(bp, ap);
    k_statsP2<<<dim3(4, 4), 128>>>();
    k_final<<<(OUT_ELEMS / 4 + 255) / 256, 256>>>(x, gp, bep, out);
    k_bufs<<<(KBUF_ELEMS + VBUF_ELEMS + 255) / 256, 256>>>(gk, bek, gv, bev,
                                                           out + OUT_ELEMS,
                                                           out + OUT_ELEMS + KBUF_ELEMS);
}

// round 16
// speedup vs baseline: 1.2584x; 1.2584x over previous
#include <cuda_runtime.h>
#include <cuda_bf16.h>
#include <math.h>

// ---------------- problem constants ----------------
#define NB   4
#define NT   500
#define NF   65
#define NC   128
#define NH   8
#define NBH  32
#define DQK  260        // F*E_DIM
#define DV   1040       // F*V_DIM
#define FC   8320       // F*C
#define EPSV 1e-5f
#define OUT_ELEMS 16640000
#define KBUF_ELEMS 74880     // 32*9*260
#define VBUF_ELEMS 299520    // 32*9*1040

typedef unsigned long long u64;
typedef unsigned int u32;
typedef unsigned short u16;

// ---------------- scratch (__device__ globals; no runtime alloc) ------------
__device__ float d_Qr [(size_t)NBH * DQK * NT];
__device__ float d_KrP[16 + (size_t)NBH * DQK * NT];
__device__ float d_VrP[16 + (size_t)NBH * DV  * NT];
#define d_Kr (d_KrP + 16)
#define d_Vr (d_VrP + 16)
__device__ float d_Z [(size_t)NB * NF * NC * NT]; // [b][f][cc][t]  cc = h*16+dv
__device__ float d_Y [(size_t)NB * NC * NF * NT]; // [b][o][f][t]
__device__ float d_muq[NBH * NT], d_rsq[NBH * NT];
__device__ float d_muk[NBH * NT], d_rsk[NBH * NT];
__device__ float d_muv[NBH * NT], d_rsv[NBH * NT];
__device__ float d_mup[NB * NT],  d_rsp[NB * NT];
__device__ float d_part_s [12 * NBH * NT], d_part_ss[12 * NBH * NT];
__device__ float d_ps [NF * NB * NT], d_pss[NF * NB * NT];
#define CFSTR (NBH * NT)
__device__ float d_cf [24 * CFSTR];
__device__ float d_dummy[1024];

// Pre-baked per-lane B fragment arrays: [nt][kk(24)][lane(32)] -> u64 (b0,b1)
// virtual K sections: kk 0..7 = Bh, 8..15 = Bl, 16..23 = Bh
__device__ u64 g_Bkv[20 * 24 * 32];   // 160 outputs (K 32 + V 128)
__device__ u64 g_Bq [4  * 24 * 32];   // 32 outputs
__device__ u64 g_Bp [16 * 24 * 32];   // 128 outputs

// ---------------- warp mma helper -------------------------------------------
__device__ __forceinline__ void mma16816(float* c, u32 a0, u32 a1, u32 a2, u32 a3,
                                         u32 b0, u32 b1) {
    asm volatile(
        "mma.sync.aligned.m16n8k16.row.col.f32.bf16.bf16.f32 "
        "{%0,%1,%2,%3}, {%4,%5,%6,%7}, {%8,%9}, {%0,%1,%2,%3};"
        : "+f"(c[0]), "+f"(c[1]), "+f"(c[2]), "+f"(c[3])
        : "r"(a0), "r"(a1), "r"(a2), "r"(a3), "r"(b0), "r"(b1));
}

// A fragment pair-store: values at (row r, channels 2*c2, 2*c2+1) packed as u32
// fragment layout [mi(8)][kf(16)][lane^mi(32)] x 16B ; kf 0..7 = Ah, 8..15 = Al
__device__ __forceinline__ void storePair(char* As, int r, int c2, float a0, float a1) {
    __nv_bfloat162 ph = __floats2bfloat162_rn(a0, a1);   // lo = a0 (even c)
    float r0 = a0 - __bfloat162float(ph.x);
    float r1 = a1 - __bfloat162float(ph.y);
    __nv_bfloat162 pl = __floats2bfloat162_rn(r0, r1);
    u32 bhp = *(u32*)&ph;
    u32 blp = *(u32*)&pl;
    int mi = r >> 4, rl = r & 15;
    int q = c2 & 3, klhi = (c2 >> 2) & 1, kf = c2 >> 3;
    int lane = (rl & 7) * 4 + q;
    int lanes = lane ^ (mi & 7);
    int sub = (rl >> 3) + 2 * klhi;
    u32* base = (u32*)As;
    base[((mi * 16 + kf) * 32 + lanes) * 4 + sub] = bhp;
    base[((mi * 16 + 8 + kf) * 32 + lanes) * 4 + sub] = blp;
}

// ---------------- warmup no-op ----------------------------------------------
__global__ void k_warm() {
    int i = blockIdx.x * 128 + threadIdx.x;
    if (i < 1024) d_dummy[i] = 0.f;
}

// ======= k_prep: bake B fragment arrays =====================================
__global__ void k_prep(const float* __restrict__ Wq, const float* __restrict__ Wk,
                       const float* __restrict__ Wv, const float* __restrict__ Wp)
{
    int idx = blockIdx.x * 256 + threadIdx.x;
    if (idx >= 40960) return;
    float w; __nv_bfloat16* img; int o, c;
    if (idx < 20480) {
        o = idx >> 7; c = idx & 127;
        w = (o < 32) ? Wk[o * 128 + c] : Wv[(o - 32) * 128 + c];
        img = (__nv_bfloat16*)g_Bkv;
    } else if (idx < 24576) {
        int i = idx - 20480; o = i >> 7; c = i & 127;
        w = Wq[o * 128 + c];
        img = (__nv_bfloat16*)g_Bq;
    } else {
        int i = idx - 24576; o = i >> 7; c = i & 127;
        w = Wp[o * 128 + c];
        img = (__nv_bfloat16*)g_Bp;
    }
    __nv_bfloat16 bh = __float2bfloat16(w);
    __nv_bfloat16 bl = __float2bfloat16(w - __bfloat162float(bh));
    int nt = o >> 3, n = o & 7;
    int kl = c & 15;
    int lane = n * 4 + ((kl & 7) >> 1);
    int sub = (kl >> 3) * 2 + (kl & 1);
#pragma unroll
    for (int s = 0; s < 3; s++) {
        int kk = s * 8 + (c >> 4);
        __nv_bfloat16 val = (s == 1) ? bl : bh;
        img[((nt * 24 + kk) * 32 + lane) * 4 + sub] = val;
    }
}

// shared A-tile build; cstride = element stride between channels in src
__device__ __forceinline__ void buildA(char* sA, const float* __restrict__ src,
                                       size_t cstride, int t0, int tid) {
    for (int i = tid; i < 64 * 32; i += 256) {
        int c2 = i >> 5, tq = i & 31;
        int t = t0 + tq * 4;
        float4 v0 = make_float4(0.f, 0.f, 0.f, 0.f);
        float4 v1 = v0;
        if (t < NT) {
            v0 = *(const float4*)(src + (size_t)(2 * c2)     * cstride + t);
            v1 = *(const float4*)(src + (size_t)(2 * c2 + 1) * cstride + t);
        }
        storePair(sA, tq * 4 + 0, c2, v0.x, v1.x);
        storePair(sA, tq * 4 + 1, c2, v0.y, v1.y);
        storePair(sA, tq * 4 + 2, c2, v0.z, v1.z);
        storePair(sA, tq * 4 + 3, c2, v0.w, v1.w);
    }
}

// ======= kernel 1a: K+V projection via mma.sync (N=160) =====================
#define GEMM_SMEM 65536
__global__ __launch_bounds__(256)
void k_kv_mma(const float* __restrict__ mc,
              const float* __restrict__ bk, const float* __restrict__ ak,
              const float* __restrict__ bv, const float* __restrict__ av)
{
    extern __shared__ char sA[];
    const int tid = threadIdx.x, wid = tid >> 5, lane = tid & 31;
    const int f = blockIdx.y, b = blockIdx.z;
    const int t0 = blockIdx.x * 128;

    buildA(sA, mc + ((size_t)(b * NC) * NF + f) * NT, (size_t)NF * NT, t0, tid);
    __syncthreads();

    float acc[20][4];
#pragma unroll
    for (int nt = 0; nt < 20; nt++)
#pragma unroll
        for (int r = 0; r < 4; r++) acc[nt][r] = 0.f;

    const int mi = wid;
    const uint4* Aptr = (const uint4*)sA + (mi * 16 * 32 + (lane ^ (mi & 7)));
#pragma unroll 1
    for (int kk = 0; kk < 24; kk++) {
        int af = (kk < 8) ? kk : kk - 8;
        uint4 A = Aptr[af * 32];
        const u64* bp = g_Bkv + kk * 32 + lane;
#pragma unroll
        for (int nt = 0; nt < 20; nt++) {
            u64 bb = bp[nt * 768];
            mma16816(acc[nt], A.x, A.y, A.z, A.w, (u32)bb, (u32)(bb >> 32));
        }
    }
    __syncthreads();

    // epilogue: transpose via smem chunks of 32 rows, coalesced STG.128
    float* sE = (float*)sA;
    const int g = lane >> 2, tg = lane & 3;
    const float akv = ak[0], avv = av[0];
#pragma unroll
    for (int ch = 0; ch < 5; ch++) {
#pragma unroll
        for (int ntL = 0; ntL < 4; ntL++)
#pragma unroll
            for (int r = 0; r < 4; r++) {
                int e = r & 1, hr = r >> 1;
                sE[(ntL * 8 + tg * 2 + e) * 132 + mi * 16 + g + 8 * hr] = acc[ch * 4 + ntL][r];
            }
        __syncthreads();
        {
            int o = tid >> 3;
            int tf = (tid & 7) * 4;
            int og = ch * 32 + o;
            float bb, al; float* dst;
            if (og < 32) {
                bb = bk[og]; al = akv;
                dst = d_Kr + ((size_t)(b * 8 + (og >> 2)) * DQK + f * 4 + (og & 3)) * NT;
            } else {
                int vv = og - 32;
                bb = bv[vv]; al = avv;
                dst = d_Vr + ((size_t)(b * 8 + (vv >> 4)) * DV + f * 16 + (vv & 15)) * NT;
            }
#pragma unroll
            for (int s = 0; s < 4; s++) {
                int tl = tf + s * 32;
                int t = t0 + tl;
                if (t < NT) {
                    float4 v = *(float4*)&sE[o * 132 + tl];
                    v.x += bb; v.x = v.x >= 0.f ? v.x : al * v.x;
                    v.y += bb; v.y = v.y >= 0.f ? v.y : al * v.y;
                    v.z += bb; v.z = v.z >= 0.f ? v.z : al * v.z;
                    v.w += bb; v.w = v.w >= 0.f ? v.w : al * v.w;
                    *(float4*)&dst[t] = v;
                }
            }
        }
        __syncthreads();
    }
}

// ======= kernel 1b: Q projection via mma.sync (N=32) ========================
__global__ __launch_bounds__(256)
void k_q_mma(const float* __restrict__ x,
             const float* __restrict__ bq, const float* __restrict__ aq)
{
    extern __shared__ char sA[];
    const int tid = threadIdx.x, wid = tid >> 5, lane = tid & 31;
    const int f = blockIdx.y, b = blockIdx.z;
    const int t0 = blockIdx.x * 128;

    buildA(sA, x + ((size_t)(b * NC) * NF + f) * NT, (size_t)NF * NT, t0, tid);
    __syncthreads();

    float acc[4][4];
#pragma unroll
    for (int nt = 0; nt < 4; nt++)
#pragma unroll
        for (int r = 0; r < 4; r++) acc[nt][r] = 0.f;

    const int mi = wid;
    const uint4* Aptr = (const uint4*)sA + (mi * 16 * 32 + (lane ^ (mi & 7)));
#pragma unroll 1
    for (int kk = 0; kk < 24; kk++) {
        int af = (kk < 8) ? kk : kk - 8;
        uint4 A = Aptr[af * 32];
        const u64* bp = g_Bq + kk * 32 + lane;
#pragma unroll
        for (int nt = 0; nt < 4; nt++) {
            u64 bb = bp[nt * 768];
            mma16816(acc[nt], A.x, A.y, A.z, A.w, (u32)bb, (u32)(bb >> 32));
        }
    }
    __syncthreads();

    float* sE = (float*)sA;
    const int g = lane >> 2, tg = lane & 3;
    const float aqv = aq[0];
#pragma unroll
    for (int ntL = 0; ntL < 4; ntL++)
#pragma unroll
        for (int r = 0; r < 4; r++) {
            int e = r & 1, hr = r >> 1;
            sE[(ntL * 8 + tg * 2 + e) * 132 + wid * 16 + g + 8 * hr] = acc[ntL][r];
        }
    __syncthreads();
    {
        int o = tid >> 3;
        int tf = (tid & 7) * 4;
        float bb = bq[o];
        float* dst = d_Qr + ((size_t)(b * 8 + (o >> 2)) * DQK + f * 4 + (o & 3)) * NT;
#pragma unroll
        for (int s = 0; s < 4; s++) {
            int tl = tf + s * 32;
            int t = t0 + tl;
            if (t < NT) {
                float4 v = *(float4*)&sE[o * 132 + tl];
                v.x += bb; v.x = v.x >= 0.f ? v.x : aqv * v.x;
                v.y += bb; v.y = v.y >= 0.f ? v.y : aqv * v.y;
                v.z += bb; v.z = v.z >= 0.f ? v.z : aqv * v.z;
                v.w += bb; v.w = v.w >= 0.f ? v.w : aqv * v.w;
                *(float4*)&dst[t] = v;
            }
        }
    }
}

// ======= kernel 4: P projection via mma.sync (N=128) + fused LN-P partials ==
__global__ __launch_bounds__(256)
void k_p_mma(const float* __restrict__ bp_, const float* __restrict__ ap)
{
    extern __shared__ char sA[];
    const int tid = threadIdx.x, wid = tid >> 5, lane = tid & 31;
    const int f = blockIdx.y, b = blockIdx.z;
    const int t0 = blockIdx.x * 128;

    buildA(sA, d_Z + ((size_t)(b * NF + f) * NC) * NT, (size_t)NT, t0, tid);
    __syncthreads();

    float acc[16][4];
#pragma unroll
    for (int nt = 0; nt < 16; nt++)
#pragma unroll
        for (int r = 0; r < 4; r++) acc[nt][r] = 0.f;

    const int mi = wid;
    const uint4* Aptr = (const uint4*)sA + (mi * 16 * 32 + (lane ^ (mi & 7)));
#pragma unroll 1
    for (int kk = 0; kk < 24; kk++) {
        int af = (kk < 8) ? kk : kk - 8;
        uint4 A = Aptr[af * 32];
        const u64* bp = g_Bp + kk * 32 + lane;
#pragma unroll
        for (int nt = 0; nt < 16; nt++) {
            u64 bb = bp[nt * 768];
            mma16816(acc[nt], A.x, A.y, A.z, A.w, (u32)bb, (u32)(bb >> 32));
        }
    }

    // LN-P partials in fragment domain (shfl over the 4 tg lanes)
    const int g = lane >> 2, tg = lane & 3;
    const float apv = ap[0];
    {
        float s_[2] = {0.f, 0.f}, ss_[2] = {0.f, 0.f};
#pragma unroll
        for (int nt = 0; nt < 16; nt++)
#pragma unroll
            for (int r = 0; r < 4; r++) {
                int e = r & 1, hr = r >> 1;
                int o = nt * 8 + tg * 2 + e;
                float v = acc[nt][r] + bp_[o];
                v = v >= 0.f ? v : apv * v;
                s_[hr] += v;
                ss_[hr] = fmaf(v, v, ss_[hr]);
            }
#pragma unroll
        for (int hr = 0; hr < 2; hr++) {
            s_[hr]  += __shfl_xor_sync(0xffffffffu, s_[hr], 1);
            s_[hr]  += __shfl_xor_sync(0xffffffffu, s_[hr], 2);
            ss_[hr] += __shfl_xor_sync(0xffffffffu, ss_[hr], 1);
            ss_[hr] += __shfl_xor_sync(0xffffffffu, ss_[hr], 2);
            int t = t0 + mi * 16 + g + 8 * hr;
            if (tg == 0 && t < NT) {
                d_ps [(f * NB + b) * NT + t] = s_[hr];
                d_pss[(f * NB + b) * NT + t] = ss_[hr];
            }
        }
    }
    __syncthreads();

    float* sE = (float*)sA;
#pragma unroll
    for (int ch = 0; ch < 4; ch++) {
#pragma unroll
        for (int ntL = 0; ntL < 4; ntL++)
#pragma unroll
            for (int r = 0; r < 4; r++) {
                int e = r & 1, hr = r >> 1;
                sE[(ntL * 8 + tg * 2 + e) * 132 + mi * 16 + g + 8 * hr] = acc[ch * 4 + ntL][r];
            }
        __syncthreads();
        {
            int o = tid >> 3;
            int tf = (tid & 7) * 4;
            int og = ch * 32 + o;
            float bb = bp_[og];
            float* dst = d_Y + ((size_t)(b * NC + og) * NF + f) * NT;
#pragma unroll
            for (int s = 0; s < 4; s++) {
                int tl = tf + s * 32;
                int t = t0 + tl;
                if (t < NT) {
                    float4 v = *(float4*)&sE[o * 132 + tl];
                    v.x += bb; v.x = v.x >= 0.f ? v.x : apv * v.x;
                    v.y += bb; v.y = v.y >= 0.f ? v.y : apv * v.y;
                    v.z += bb; v.z = v.z >= 0.f ? v.z : apv * v.z;
                    v.w += bb; v.w = v.w >= 0.f ? v.w : apv * v.w;
                    *(float4*)&dst[t] = v;
                }
            }
        }
        __syncthreads();
    }
}

// ============ kernel 2: merged Q/K/V LN stats, split-d partials =============
__global__ void k_stats_part() {
    int t = blockIdx.x * 128 + threadIdx.x;
    if (t >= NT) return;
    int bh = blockIdx.y, s = blockIdx.z;
    const float* p;
    if (s < 2)      p = d_Qr + ((size_t)bh * DQK + s * 130) * NT + t;
    else if (s < 4) p = d_Kr + ((size_t)bh * DQK + (s - 2) * 130) * NT + t;
    else            p = d_Vr + ((size_t)bh * DV  + (s - 4) * 130) * NT + t;
    float sum = 0.f, ss = 0.f;
#pragma unroll 10
    for (int i = 0; i < 130; i++) { float v = p[(size_t)i * NT]; sum += v; ss += v * v; }
    int o = (s * NBH + bh) * NT + t;
    d_part_s[o] = sum;
    d_part_ss[o] = ss;
}
__global__ void k_stats_comb() {
    int t = blockIdx.x * 128 + threadIdx.x;
    if (t >= NT) return;
    int bh = blockIdx.y;
    float s, ss, m, var;
    s = d_part_s[(0 * NBH + bh) * NT + t] + d_part_s[(1 * NBH + bh) * NT + t];
    ss = d_part_ss[(0 * NBH + bh) * NT + t] + d_part_ss[(1 * NBH + bh) * NT + t];
    m = s * (1.f / DQK); var = ss * (1.f / DQK) - m * m;
    d_muq[bh * NT + t] = m; d_rsq[bh * NT + t] = rsqrtf(var + EPSV);
    s = d_part_s[(2 * NBH + bh) * NT + t] + d_part_s[(3 * NBH + bh) * NT + t];
    ss = d_part_ss[(2 * NBH + bh) * NT + t] + d_part_ss[(3 * NBH + bh) * NT + t];
    m = s * (1.f / DQK); var = ss * (1.f / DQK) - m * m;
    d_muk[bh * NT + t] = m; d_rsk[bh * NT + t] = rsqrtf(var + EPSV);
    s = 0.f; ss = 0.f;
#pragma unroll
    for (int sl = 4; sl < 12; sl++) {
        s += d_part_s[(sl * NBH + bh) * NT + t];
        ss += d_part_ss[(sl * NBH + bh) * NT + t];
    }
    m = s * (1.f / DV); var = ss * (1.f / DV) - m * m;
    d_muv[bh * NT + t] = m; d_rsv[bh * NT + t] = rsqrtf(var + EPSV);
}

// ========== kernel 3a: scores + softmax -> coefficient vectors (SoA) ========
__global__ __launch_bounds__(128)
void k_score(const float* __restrict__ Kbuf,
             const float* __restrict__ gq, const float* __restrict__ beq,
             const float* __restrict__ gk, const float* __restrict__ bek)
{
    __shared__ float sp[32][4][4][12];

    const int tid = threadIdx.x;
    const int tl = tid & 3, dg = tid >> 2;
    const int bh = blockIdx.y;
    const int t0 = blockIdx.x * 16;
    const int t4 = t0 + 4 * tl;
    const int t4c = (t4 < NT) ? t4 : (NT - 4);

    const float* Qp = d_Qr + (size_t)bh * DQK * NT;
    const float* Kp = d_Kr + (size_t)bh * DQK * NT;

    {
        const float4 muq4 = *(const float4*)(d_muq + bh * NT + t4c);
        const float4 rsq4 = *(const float4*)(d_rsq + bh * NT + t4c);
        const float mu[4] = {muq4.x, muq4.y, muq4.z, muq4.w};
        const float rs[4] = {rsq4.x, rsq4.y, rsq4.z, rsq4.w};
        float s[4][10];
#pragma unroll
        for (int j = 0; j < 4; j++)
#pragma unroll
            for (int c = 0; c < 10; c++) s[j][c] = 0.f;
        float Qg[4] = {0.f, 0.f, 0.f, 0.f}, Qb[4] = {0.f, 0.f, 0.f, 0.f};

        int d0 = dg * 9, d1 = d0 + 9; if (d1 > DQK) d1 = DQK;
        for (int d = d0; d < d1; d++) {
            const float4 q4 = *(const float4*)(Qp + (size_t)d * NT + t4c);
            const float qv[4] = {q4.x, q4.y, q4.z, q4.w};
            const float gqd = gq[d], beqd = beq[d], gkd = gk[d], bekd = bek[d];
            float w[16];
            const float* kb = Kp + (size_t)d * NT + t4c - 12;
            *(float4*)&w[0]  = *(const float4*)(kb);
            *(float4*)&w[4]  = *(const float4*)(kb + 4);
            *(float4*)&w[8]  = *(const float4*)(kb + 8);
            *(float4*)&w[12] = *(const float4*)(kb + 12);
            float qg[4];
#pragma unroll
            for (int j = 0; j < 4; j++) {
                float qn = fmaf((qv[j] - mu[j]) * rs[j], gqd, beqd);
                qg[j] = qn * gkd;
                Qg[j] += qg[j];
                Qb[j] = fmaf(qn, bekd, Qb[j]);
            }
#pragma unroll
            for (int c = 0; c < 10; c++)
#pragma unroll
                for (int j = 0; j < 4; j++)
                    s[j][c] = fmaf(qg[j], w[3 + j + c], s[j][c]);
        }
#pragma unroll
        for (int j = 0; j < 4; j++) {
#pragma unroll
            for (int c = 0; c < 10; c++) sp[dg][tl][j][c] = s[j][c];
            sp[dg][tl][j][10] = Qg[j];
            sp[dg][tl][j][11] = Qb[j];
        }
    }
    __syncthreads();

    if (tid < 16) {
        const int tt = tid, jj = tt & 3, tln = tt >> 2;
        int t = t0 + tt;
        if (t >= NT) return;
        const int tc = t;
        float S[10], QG = 0.f, QB = 0.f;
#pragma unroll
        for (int c = 0; c < 10; c++) S[c] = 0.f;
#pragma unroll
        for (int g = 0; g < 32; g++) {
#pragma unroll
            for (int c = 0; c < 10; c++) S[c] += sp[g][tln][jj][c];
            QG += sp[g][tln][jj][10];
            QB += sp[g][tln][jj][11];
        }
        const int c0 = (tc < 9) ? (9 - tc) : 0;
#pragma unroll
        for (int c = 0; c < 10; c++) {
            int src = tc + c - 9;
            int sc = src < 0 ? 0 : src;
            float mk = d_muk[bh * NT + sc], rk = d_rsk[bh * NT + sc];
            S[c] = rk * (S[c] - mk * QG) + QB;
        }
        if (c0 > 0) {
            const float muq = d_muq[bh * NT + tc], rsq = d_rsq[bh * NT + tc];
            for (int c = 0; c < c0; c++) {
                const float* kb = Kbuf + ((size_t)bh * 9 + (tc + c)) * DQK;
                float acc = 0.f;
                for (int d = 0; d < DQK; d++) {
                    float qr = Qp[(size_t)d * NT + tc];
                    float qn = (qr - muq) * rsq * gq[d] + beq[d];
                    acc = fmaf(qn, kb[d], acc);
                }
                S[c] = acc;
            }
        }
        const float SCL = 0.0620173672946042252f;  // 1/sqrt(260)
        float mx = -1e30f;
#pragma unroll
        for (int c = 0; c < 10; c++) { S[c] *= SCL; mx = fmaxf(mx, S[c]); }
        float p[10], psum = 0.f;
#pragma unroll
        for (int c = 0; c < 10; c++) { p[c] = expf(S[c] - mx); psum += p[c]; }
        float inv = 1.f / psum;
        const int cfo = bh * NT + t;
        float boff = 0.f, P = 0.f;
#pragma unroll
        for (int c = 0; c < 10; c++) {
            p[c] *= inv;
            d_cf[c * CFSTR + cfo] = p[c];
            int src = tc + c - 9;
            float a = 0.f;
            if (src >= 0) {
                float mv_ = d_muv[bh * NT + src], rv_ = d_rsv[bh * NT + src];
                a = p[c] * rv_;
                boff -= a * mv_;
                P += p[c];
            }
            d_cf[(10 + c) * CFSTR + cfo] = a;
        }
        d_cf[20 * CFSTR + cfo] = boff;
        d_cf[21 * CFSTR + cfo] = P;
    }
}

// ========== kernel 3b: Vo FIR ===============================================
__global__ __launch_bounds__(256)
void k_vo(const float* __restrict__ Vbuf,
          const float* __restrict__ gv, const float* __restrict__ bev)
{
    const int tid = threadIdx.x;
    const int tl = tid & 31, dl = tid >> 5;
    const int bh = blockIdx.z;
    const int b = bh >> 3, h = bh & 7;
    const int t4 = blockIdx.x * 128 + 4 * tl;
    const bool vld = t4 < NT;
    const int t4c = vld ? t4 : (NT - 4);
    const int dbase = blockIdx.y * 80 + dl * 10;
    const int cfo = bh * NT + t4c;

    float a[4][10], boff[4], Pv[4];
#pragma unroll
    for (int c = 0; c < 10; c++) {
        float4 a4 = *(const float4*)(d_cf + (10 + c) * CFSTR + cfo);
        a[0][c] = a4.x; a[1][c] = a4.y; a[2][c] = a4.z; a[3][c] = a4.w;
    }
    {
        float4 b4 = *(const float4*)(d_cf + 20 * CFSTR + cfo);
        boff[0] = b4.x; boff[1] = b4.y; boff[2] = b4.z; boff[3] = b4.w;
        float4 p4 = *(const float4*)(d_cf + 21 * CFSTR + cfo);
        Pv[0] = p4.x; Pv[1] = p4.y; Pv[2] = p4.z; Pv[3] = p4.w;
    }
    const bool anybuf = (t4c < 9);
    const float* Vp = d_Vr + (size_t)bh * DV * NT;

#pragma unroll 2
    for (int i = 0; i < 10; i++) {
        const int d = dbase + i;
        float w[16];
        const float* vb = Vp + (size_t)d * NT + t4c - 12;
        *(float4*)&w[0]  = *(const float4*)(vb);
        *(float4*)&w[4]  = *(const float4*)(vb + 4);
        *(float4*)&w[8]  = *(const float4*)(vb + 8);
        *(float4*)&w[12] = *(const float4*)(vb + 12);
        float acc[4] = {boff[0], boff[1], boff[2], boff[3]};
#pragma unroll
        for (int c = 0; c < 10; c++)
#pragma unroll
            for (int j = 0; j < 4; j++)
                acc[j] = fmaf(a[j][c], w[3 + j + c], acc[j]);
        const float gvd = gv[d], bevd = bev[d];
        float vo[4];
#pragma unroll
        for (int j = 0; j < 4; j++) vo[j] = fmaf(gvd, acc[j], bevd * Pv[j]);
        if (anybuf) {
#pragma unroll
            for (int j = 0; j < 4; j++) {
                int tj = t4c + j;
                int cb = 9 - tj;
                for (int c = 0; c < cb; c++)
                    vo[j] = fmaf(d_cf[c * CFSTR + bh * NT + tj],
                                 Vbuf[((size_t)bh * 9 + (tj + c)) * DV + d], vo[j]);
            }
        }
        if (vld) {
            int f = d >> 4, dvv = d & 15;
            float4 o4 = make_float4(vo[0], vo[1], vo[2], vo[3]);
            *(float4*)(d_Z + (((size_t)b * NF + f) * NC + h * 16 + dvv) * NT + t4) = o4;
        }
    }
}

// ============ kernel 5: LN-P stats combine over 65 f-partials ===============
__global__ void k_statsP2() {
    int t = blockIdx.x * 128 + threadIdx.x;
    if (t >= NT) return;
    int b = blockIdx.y;
    float s = 0.f, ss = 0.f;
#pragma unroll 5
    for (int f = 0; f < NF; f++) {
        s += d_ps [(f * NB + b) * NT + t];
        ss += d_pss[(f * NB + b) * NT + t];
    }
    float m = s * (1.f / FC);
    float var = ss * (1.f / FC) - m * m;
    d_mup[b * NT + t] = m;
    d_rsp[b * NT + t] = rsqrtf(var + EPSV);
}

// ========== kernel 6: LN-P apply + residual + output (float4) ===============
__global__ void k_final(const float* __restrict__ x, const float* __restrict__ gp,
                        const float* __restrict__ bep, float* __restrict__ out)
{
    size_t idx4 = (size_t)blockIdx.x * 256 + threadIdx.x;
    if (idx4 >= (size_t)(OUT_ELEMS / 4)) return;
    size_t i = idx4 * 4;
    int t = (int)(i % NT);
    size_t r = i / NT;
    int f = (int)(r % NF); r /= NF;
    int o = (int)(r % NC);
    int b = (int)(r / NC);
    float4 y = *(const float4*)(d_Y + i);
    float4 xv = *(const float4*)(x + i);
    float4 m4 = *(const float4*)(d_mup + b * NT + t);
    float4 r4 = *(const float4*)(d_rsp + b * NT + t);
    int gi = f * NC + o;
    float g = gp[gi], be = bep[gi];
    float4 ov;
    ov.x = (y.x - m4.x) * r4.x * g + be + xv.x;
    ov.y = (y.y - m4.y) * r4.y * g + be + xv.y;
    ov.z = (y.z - m4.z) * r4.z * g + be + xv.z;
    ov.w = (y.w - m4.w) * r4.w * g + be + xv.w;
    *(float4*)(out + i) = ov;
}

// ================= kernel 7: K_buf_new / V_buf_new ==========================
__global__ void k_bufs(const float* __restrict__ gk, const float* __restrict__ bek,
                       const float* __restrict__ gv, const float* __restrict__ bev,
                       float* __restrict__ kout, float* __restrict__ vout)
{
    int idx = blockIdx.x * 256 + threadIdx.x;
    if (idx < KBUF_ELEMS) {
        int d = idx % DQK; int r = idx / DQK; int j = r % 9; int bh = r / 9;
        int t = 491 + j;
        float v = d_Kr[((size_t)bh * DQK + d) * NT + t];
        v = (v - d_muk[bh * NT + t]) * d_rsk[bh * NT + t] * gk[d] + bek[d];
        kout[idx] = v;
    } else {
        int i2 = idx - KBUF_ELEMS;
        if (i2 < VBUF_ELEMS) {
            int d = i2 % DV; int r = i2 / DV; int j = r % 9; int bh = r / 9;
            int t = 491 + j;
            float v = d_Vr[((size_t)bh * DV + d) * NT + t];
            v = (v - d_muv[bh * NT + t]) * d_rsv[bh * NT + t] * gv[d] + bev[d];
            vout[i2] = v;
        }
    }
}

// ================= launch ==================================================
extern "C" void kernel_launch(void* const* d_in, const int* in_sizes, int n_in,
                              void* d_out, int out_size)
{
    const float* x    = (const float*)d_in[0];
    const float* mc   = (const float*)d_in[1];
    const float* Kbuf = (const float*)d_in[2];
    const float* Vbuf = (const float*)d_in[3];
    const float* Wq   = (const float*)d_in[4];
    const float* bq   = (const float*)d_in[5];
    const float* aq   = (const float*)d_in[6];
    const float* gq   = (const float*)d_in[7];
    const float* beq  = (const float*)d_in[8];
    const float* Wk   = (const float*)d_in[9];
    const float* bk   = (const float*)d_in[10];
    const float* ak   = (const float*)d_in[11];
    const float* gk   = (const float*)d_in[12];
    const float* bek  = (const float*)d_in[13];
    const float* Wv   = (const float*)d_in[14];
    const float* bv   = (const float*)d_in[15];
    const float* av   = (const float*)d_in[16];
    const float* gv   = (const float*)d_in[17];
    const float* bev  = (const float*)d_in[18];
    const float* Wp   = (const float*)d_in[19];
    const float* bp   = (const float*)d_in[20];
    const float* ap   = (const float*)d_in[21];
    const float* gp   = (const float*)d_in[22];
    const float* bep  = (const float*)d_in[23];
    float* out = (float*)d_out;

    cudaFuncSetAttribute(k_kv_mma, cudaFuncAttributeMaxDynamicSharedMemorySize, GEMM_SMEM);
    cudaFuncSetAttribute(k_q_mma,  cudaFuncAttributeMaxDynamicSharedMemorySize, GEMM_SMEM);
    cudaFuncSetAttribute(k_p_mma,  cudaFuncAttributeMaxDynamicSharedMemorySize, GEMM_SMEM);

    // slots 0-2: warm + prep, so ncu's captured launch (index 3) = k_kv_mma
    k_warm<<<8, 128>>>();
    k_warm<<<8, 128>>>();
    k_prep<<<160, 256>>>(Wq, Wk, Wv, Wp);
    k_kv_mma<<<dim3(4, 65, 4), 256, GEMM_SMEM>>>(mc, bk, ak, bv, av);
    k_q_mma<<<dim3(4, 65, 4), 256, GEMM_SMEM>>>(x, bq, aq);
    k_stats_part<<<dim3(4, 32, 12), 128>>>();
    k_stats_comb<<<dim3(4, 32), 128>>>();
    k_score<<<dim3(32, 32), 128>>>(Kbuf, gq, beq, gk, bek);
    k_vo<<<dim3(4, 13, 32), 256>>>(Vbuf, gv, bev);
    k_p_mma<<<dim3(4, 65, 4), 256, GEMM_SMEM>>>(bp, ap);
    k_statsP2<<<dim3(4, 4), 128>>>();
    k_final<<<(OUT_ELEMS / 4 + 255) / 256, 256>>>(x, gp, bep, out);
    k_bufs<<<(KBUF_ELEMS + VBUF_ELEMS + 255) / 256, 256>>>(gk, bek, gv, bev,
                                                           out + OUT_ELEMS,
                                                           out + OUT_ELEMS + KBUF_ELEMS);
}

// round 17
// speedup vs baseline: 1.4985x; 1.1908x over previous
#include <cuda_runtime.h>
#include <cuda_bf16.h>
#include <math.h>

// ---------------- problem constants ----------------
#define NB   4
#define NT   500
#define NF   65
#define NC   128
#define NH   8
#define NBH  32
#define DQK  260        // F*E_DIM
#define DV   1040       // F*V_DIM
#define FC   8320       // F*C
#define EPSV 1e-5f
#define OUT_ELEMS 16640000
#define KBUF_ELEMS 74880     // 32*9*260
#define VBUF_ELEMS 299520    // 32*9*1040

typedef unsigned long long u64;
typedef unsigned int u32;
typedef unsigned short u16;

// ---------------- scratch (__device__ globals; no runtime alloc) ------------
__device__ float d_Qr [(size_t)NBH * DQK * NT];
__device__ float d_KrP[16 + (size_t)NBH * DQK * NT];
__device__ float d_VrP[16 + (size_t)NBH * DV  * NT];
#define d_Kr (d_KrP + 16)
#define d_Vr (d_VrP + 16)
__device__ float d_Z [(size_t)NB * NF * NC * NT]; // [b][f][cc][t]  cc = h*16+dv
__device__ float d_Y [(size_t)NB * NC * NF * NT]; // [b][o][f][t]
__device__ float d_muq[NBH * NT], d_rsq[NBH * NT];
__device__ float d_muk[NBH * NT], d_rsk[NBH * NT];
__device__ float d_muv[NBH * NT], d_rsv[NBH * NT];
__device__ float d_mup[NB * NT],  d_rsp[NB * NT];
__device__ float d_part_s [12 * NBH * NT], d_part_ss[12 * NBH * NT];
__device__ float d_ps [NF * NB * NT], d_pss[NF * NB * NT];
#define CFSTR (NBH * NT)
__device__ float d_cf [24 * CFSTR];
__device__ float d_dummy[1024];

// Pre-baked per-lane B fragment arrays: [nt][kk(16)][lane(32)] -> u64 (b0,b1)
// kk 0..7 = Bh sections, kk 8..15 = Bl sections
__device__ u64 g_Bkv[20 * 16 * 32];   // 160 outputs (K 32 + V 128)
__device__ u64 g_Bq [4  * 16 * 32];   // 32 outputs
__device__ u64 g_Bp [16 * 16 * 32];   // 128 outputs

// ---------------- warp mma helper -------------------------------------------
__device__ __forceinline__ void mma16816(float* c, u32 a0, u32 a1, u32 a2, u32 a3,
                                         u32 b0, u32 b1) {
    asm volatile(
        "mma.sync.aligned.m16n8k16.row.col.f32.bf16.bf16.f32 "
        "{%0,%1,%2,%3}, {%4,%5,%6,%7}, {%8,%9}, {%0,%1,%2,%3};"
        : "+f"(c[0]), "+f"(c[1]), "+f"(c[2]), "+f"(c[3])
        : "r"(a0), "r"(a1), "r"(a2), "r"(a3), "r"(b0), "r"(b1));
}

// A fragment pair-store: values at (row r, channels 2*c2, 2*c2+1) packed as u32
// fragment layout [mi(8)][kf(16)][lane^mi(32)] x 16B ; kf 0..7 = Ah, 8..15 = Al
__device__ __forceinline__ void storePair(char* As, int r, int c2, float a0, float a1) {
    __nv_bfloat162 ph = __floats2bfloat162_rn(a0, a1);   // lo = a0 (even c)
    float r0 = a0 - __bfloat162float(ph.x);
    float r1 = a1 - __bfloat162float(ph.y);
    __nv_bfloat162 pl = __floats2bfloat162_rn(r0, r1);
    u32 bhp = *(u32*)&ph;
    u32 blp = *(u32*)&pl;
    int mi = r >> 4, rl = r & 15;
    int q = c2 & 3, klhi = (c2 >> 2) & 1, kf = c2 >> 3;
    int lane = (rl & 7) * 4 + q;
    int lanes = lane ^ (mi & 7);
    int sub = (rl >> 3) + 2 * klhi;
    u32* base = (u32*)As;
    base[((mi * 16 + kf) * 32 + lanes) * 4 + sub] = bhp;
    base[((mi * 16 + 8 + kf) * 32 + lanes) * 4 + sub] = blp;
}

// ---------------- warmup no-op ----------------------------------------------
__global__ void k_warm() {
    int i = blockIdx.x * 128 + threadIdx.x;
    if (i < 1024) d_dummy[i] = 0.f;
}

// ======= k_prep: bake B fragment arrays (16 kk sections) ====================
__global__ void k_prep(const float* __restrict__ Wq, const float* __restrict__ Wk,
                       const float* __restrict__ Wv, const float* __restrict__ Wp)
{
    int idx = blockIdx.x * 256 + threadIdx.x;
    if (idx >= 40960) return;
    float w; __nv_bfloat16* img; int o, c;
    if (idx < 20480) {
        o = idx >> 7; c = idx & 127;
        w = (o < 32) ? Wk[o * 128 + c] : Wv[(o - 32) * 128 + c];
        img = (__nv_bfloat16*)g_Bkv;
    } else if (idx < 24576) {
        int i = idx - 20480; o = i >> 7; c = i & 127;
        w = Wq[o * 128 + c];
        img = (__nv_bfloat16*)g_Bq;
    } else {
        int i = idx - 24576; o = i >> 7; c = i & 127;
        w = Wp[o * 128 + c];
        img = (__nv_bfloat16*)g_Bp;
    }
    __nv_bfloat16 bh = __float2bfloat16(w);
    __nv_bfloat16 bl = __float2bfloat16(w - __bfloat162float(bh));
    int nt = o >> 3, n = o & 7;
    int kl = c & 15;
    int lane = n * 4 + ((kl & 7) >> 1);
    int sub = (kl >> 3) * 2 + (kl & 1);
#pragma unroll
    for (int s = 0; s < 2; s++) {
        int kk = s * 8 + (c >> 4);
        __nv_bfloat16 val = (s == 1) ? bl : bh;
        img[((nt * 16 + kk) * 32 + lane) * 4 + sub] = val;
    }
}

// shared A-tile build; cstride = element stride between channels in src
__device__ __forceinline__ void buildA(char* sA, const float* __restrict__ src,
                                       size_t cstride, int t0, int tid) {
    for (int i = tid; i < 64 * 32; i += 256) {
        int c2 = i >> 5, tq = i & 31;
        int t = t0 + tq * 4;
        float4 v0 = make_float4(0.f, 0.f, 0.f, 0.f);
        float4 v1 = v0;
        if (t < NT) {
            v0 = *(const float4*)(src + (size_t)(2 * c2)     * cstride + t);
            v1 = *(const float4*)(src + (size_t)(2 * c2 + 1) * cstride + t);
        }
        storePair(sA, tq * 4 + 0, c2, v0.x, v1.x);
        storePair(sA, tq * 4 + 1, c2, v0.y, v1.y);
        storePair(sA, tq * 4 + 2, c2, v0.z, v1.z);
        storePair(sA, tq * 4 + 3, c2, v0.w, v1.w);
    }
}

// ======= kernel 1: K+V (z<4) and Q (z>=4) projections via mma.sync ==========
#define GEMM_SMEM 65536
__global__ __launch_bounds__(256)
void k_kvq_mma(const float* __restrict__ mc, const float* __restrict__ x,
               const float* __restrict__ bk, const float* __restrict__ ak,
               const float* __restrict__ bv, const float* __restrict__ av,
               const float* __restrict__ bq, const float* __restrict__ aq)
{
    extern __shared__ char sA[];
    const int tid = threadIdx.x, wid = tid >> 5, lane = tid & 31;
    const int f = blockIdx.y;
    const int b = blockIdx.z & 3;
    const bool isQ = (blockIdx.z >> 2) != 0;
    const int t0 = blockIdx.x * 128;

    const float* src = isQ ? x : mc;
    buildA(sA, src + ((size_t)(b * NC) * NF + f) * NT, (size_t)NF * NT, t0, tid);
    __syncthreads();

    const int mi = wid;
    const uint4* Aptr = (const uint4*)sA + (mi * 16 * 32 + (lane ^ (mi & 7)));
    const int g = lane >> 2, tg = lane & 3;
    float* sE = (float*)sA;

    if (!isQ) {
        float acc[20][4];
#pragma unroll
        for (int nt = 0; nt < 20; nt++)
#pragma unroll
            for (int r = 0; r < 4; r++) acc[nt][r] = 0.f;

#pragma unroll 1
        for (int k0 = 0; k0 < 8; k0++) {
            uint4 Ah = Aptr[k0 * 32];
            uint4 Al = Aptr[(8 + k0) * 32];
            const u64* bp = g_Bkv + k0 * 32 + lane;
#pragma unroll
            for (int nt = 0; nt < 20; nt++) {
                u64 bh_ = bp[nt * 512];
                mma16816(acc[nt], Ah.x, Ah.y, Ah.z, Ah.w, (u32)bh_, (u32)(bh_ >> 32));
                mma16816(acc[nt], Al.x, Al.y, Al.z, Al.w, (u32)bh_, (u32)(bh_ >> 32));
                u64 bl_ = bp[nt * 512 + 256];
                mma16816(acc[nt], Ah.x, Ah.y, Ah.z, Ah.w, (u32)bl_, (u32)(bl_ >> 32));
            }
        }
        __syncthreads();

        const float akv = ak[0], avv = av[0];
#pragma unroll
        for (int ch = 0; ch < 5; ch++) {
#pragma unroll
            for (int ntL = 0; ntL < 4; ntL++)
#pragma unroll
                for (int r = 0; r < 4; r++) {
                    int e = r & 1, hr = r >> 1;
                    sE[(ntL * 8 + tg * 2 + e) * 132 + mi * 16 + g + 8 * hr] = acc[ch * 4 + ntL][r];
                }
            __syncthreads();
            {
                int o = tid >> 3;
                int tf = (tid & 7) * 4;
                int og = ch * 32 + o;
                float bb, al; float* dst;
                if (og < 32) {
                    bb = bk[og]; al = akv;
                    dst = d_Kr + ((size_t)(b * 8 + (og >> 2)) * DQK + f * 4 + (og & 3)) * NT;
                } else {
                    int vv = og - 32;
                    bb = bv[vv]; al = avv;
                    dst = d_Vr + ((size_t)(b * 8 + (vv >> 4)) * DV + f * 16 + (vv & 15)) * NT;
                }
#pragma unroll
                for (int s = 0; s < 4; s++) {
                    int tl = tf + s * 32;
                    int t = t0 + tl;
                    if (t < NT) {
                        float4 v = *(float4*)&sE[o * 132 + tl];
                        v.x += bb; v.x = v.x >= 0.f ? v.x : al * v.x;
                        v.y += bb; v.y = v.y >= 0.f ? v.y : al * v.y;
                        v.z += bb; v.z = v.z >= 0.f ? v.z : al * v.z;
                        v.w += bb; v.w = v.w >= 0.f ? v.w : al * v.w;
                        *(float4*)&dst[t] = v;
                    }
                }
            }
            __syncthreads();
        }
    } else {
        float acc[4][4];
#pragma unroll
        for (int nt = 0; nt < 4; nt++)
#pragma unroll
            for (int r = 0; r < 4; r++) acc[nt][r] = 0.f;

#pragma unroll 1
        for (int k0 = 0; k0 < 8; k0++) {
            uint4 Ah = Aptr[k0 * 32];
            uint4 Al = Aptr[(8 + k0) * 32];
            const u64* bp = g_Bq + k0 * 32 + lane;
#pragma unroll
            for (int nt = 0; nt < 4; nt++) {
                u64 bh_ = bp[nt * 512];
                mma16816(acc[nt], Ah.x, Ah.y, Ah.z, Ah.w, (u32)bh_, (u32)(bh_ >> 32));
                mma16816(acc[nt], Al.x, Al.y, Al.z, Al.w, (u32)bh_, (u32)(bh_ >> 32));
                u64 bl_ = bp[nt * 512 + 256];
                mma16816(acc[nt], Ah.x, Ah.y, Ah.z, Ah.w, (u32)bl_, (u32)(bl_ >> 32));
            }
        }
        __syncthreads();

        const float aqv = aq[0];
#pragma unroll
        for (int ntL = 0; ntL < 4; ntL++)
#pragma unroll
            for (int r = 0; r < 4; r++) {
                int e = r & 1, hr = r >> 1;
                sE[(ntL * 8 + tg * 2 + e) * 132 + mi * 16 + g + 8 * hr] = acc[ntL][r];
            }
        __syncthreads();
        {
            int o = tid >> 3;
            int tf = (tid & 7) * 4;
            float bb = bq[o];
            float* dst = d_Qr + ((size_t)(b * 8 + (o >> 2)) * DQK + f * 4 + (o & 3)) * NT;
#pragma unroll
            for (int s = 0; s < 4; s++) {
                int tl = tf + s * 32;
                int t = t0 + tl;
                if (t < NT) {
                    float4 v = *(float4*)&sE[o * 132 + tl];
                    v.x += bb; v.x = v.x >= 0.f ? v.x : aqv * v.x;
                    v.y += bb; v.y = v.y >= 0.f ? v.y : aqv * v.y;
                    v.z += bb; v.z = v.z >= 0.f ? v.z : aqv * v.z;
                    v.w += bb; v.w = v.w >= 0.f ? v.w : aqv * v.w;
                    *(float4*)&dst[t] = v;
                }
            }
        }
    }
}

// ======= kernel 4: P projection via mma.sync (N=128) + fused LN-P partials ==
__global__ __launch_bounds__(256)
void k_p_mma(const float* __restrict__ bp_, const float* __restrict__ ap)
{
    extern __shared__ char sA[];
    const int tid = threadIdx.x, wid = tid >> 5, lane = tid & 31;
    const int f = blockIdx.y, b = blockIdx.z;
    const int t0 = blockIdx.x * 128;

    buildA(sA, d_Z + ((size_t)(b * NF + f) * NC) * NT, (size_t)NT, t0, tid);
    __syncthreads();

    float acc[16][4];
#pragma unroll
    for (int nt = 0; nt < 16; nt++)
#pragma unroll
        for (int r = 0; r < 4; r++) acc[nt][r] = 0.f;

    const int mi = wid;
    const uint4* Aptr = (const uint4*)sA + (mi * 16 * 32 + (lane ^ (mi & 7)));
#pragma unroll 1
    for (int k0 = 0; k0 < 8; k0++) {
        uint4 Ah = Aptr[k0 * 32];
        uint4 Al = Aptr[(8 + k0) * 32];
        const u64* bp = g_Bp + k0 * 32 + lane;
#pragma unroll
        for (int nt = 0; nt < 16; nt++) {
            u64 bh_ = bp[nt * 512];
            mma16816(acc[nt], Ah.x, Ah.y, Ah.z, Ah.w, (u32)bh_, (u32)(bh_ >> 32));
            mma16816(acc[nt], Al.x, Al.y, Al.z, Al.w, (u32)bh_, (u32)(bh_ >> 32));
            u64 bl_ = bp[nt * 512 + 256];
            mma16816(acc[nt], Ah.x, Ah.y, Ah.z, Ah.w, (u32)bl_, (u32)(bl_ >> 32));
        }
    }

    // LN-P partials in fragment domain (shfl over the 4 tg lanes)
    const int g = lane >> 2, tg = lane & 3;
    const float apv = ap[0];
    {
        float s_[2] = {0.f, 0.f}, ss_[2] = {0.f, 0.f};
#pragma unroll
        for (int nt = 0; nt < 16; nt++)
#pragma unroll
            for (int r = 0; r < 4; r++) {
                int e = r & 1, hr = r >> 1;
                int o = nt * 8 + tg * 2 + e;
                float v = acc[nt][r] + bp_[o];
                v = v >= 0.f ? v : apv * v;
                s_[hr] += v;
                ss_[hr] = fmaf(v, v, ss_[hr]);
            }
#pragma unroll
        for (int hr = 0; hr < 2; hr++) {
            s_[hr]  += __shfl_xor_sync(0xffffffffu, s_[hr], 1);
            s_[hr]  += __shfl_xor_sync(0xffffffffu, s_[hr], 2);
            ss_[hr] += __shfl_xor_sync(0xffffffffu, ss_[hr], 1);
            ss_[hr] += __shfl_xor_sync(0xffffffffu, ss_[hr], 2);
            int t = t0 + mi * 16 + g + 8 * hr;
            if (tg == 0 && t < NT) {
                d_ps [(f * NB + b) * NT + t] = s_[hr];
                d_pss[(f * NB + b) * NT + t] = ss_[hr];
            }
        }
    }
    __syncthreads();

    float* sE = (float*)sA;
#pragma unroll
    for (int ch = 0; ch < 4; ch++) {
#pragma unroll
        for (int ntL = 0; ntL < 4; ntL++)
#pragma unroll
            for (int r = 0; r < 4; r++) {
                int e = r & 1, hr = r >> 1;
                sE[(ntL * 8 + tg * 2 + e) * 132 + mi * 16 + g + 8 * hr] = acc[ch * 4 + ntL][r];
            }
        __syncthreads();
        {
            int o = tid >> 3;
            int tf = (tid & 7) * 4;
            int og = ch * 32 + o;
            float bb = bp_[og];
            float* dst = d_Y + ((size_t)(b * NC + og) * NF + f) * NT;
#pragma unroll
            for (int s = 0; s < 4; s++) {
                int tl = tf + s * 32;
                int t = t0 + tl;
                if (t < NT) {
                    float4 v = *(float4*)&sE[o * 132 + tl];
                    v.x += bb; v.x = v.x >= 0.f ? v.x : apv * v.x;
                    v.y += bb; v.y = v.y >= 0.f ? v.y : apv * v.y;
                    v.z += bb; v.z = v.z >= 0.f ? v.z : apv * v.z;
                    v.w += bb; v.w = v.w >= 0.f ? v.w : apv * v.w;
                    *(float4*)&dst[t] = v;
                }
            }
        }
        __syncthreads();
    }
}

// ============ kernel 2: merged Q/K/V LN stats, split-d partials =============
__global__ void k_stats_part() {
    int t = blockIdx.x * 128 + threadIdx.x;
    if (t >= NT) return;
    int bh = blockIdx.y, s = blockIdx.z;
    const float* p;
    if (s < 2)      p = d_Qr + ((size_t)bh * DQK + s * 130) * NT + t;
    else if (s < 4) p = d_Kr + ((size_t)bh * DQK + (s - 2) * 130) * NT + t;
    else            p = d_Vr + ((size_t)bh * DV  + (s - 4) * 130) * NT + t;
    float sum = 0.f, ss = 0.f;
#pragma unroll 10
    for (int i = 0; i < 130; i++) { float v = p[(size_t)i * NT]; sum += v; ss += v * v; }
    int o = (s * NBH + bh) * NT + t;
    d_part_s[o] = sum;
    d_part_ss[o] = ss;
}
__global__ void k_stats_comb() {
    int t = blockIdx.x * 128 + threadIdx.x;
    if (t >= NT) return;
    int bh = blockIdx.y;
    float s, ss, m, var;
    s = d_part_s[(0 * NBH + bh) * NT + t] + d_part_s[(1 * NBH + bh) * NT + t];
    ss = d_part_ss[(0 * NBH + bh) * NT + t] + d_part_ss[(1 * NBH + bh) * NT + t];
    m = s * (1.f / DQK); var = ss * (1.f / DQK) - m * m;
    d_muq[bh * NT + t] = m; d_rsq[bh * NT + t] = rsqrtf(var + EPSV);
    s = d_part_s[(2 * NBH + bh) * NT + t] + d_part_s[(3 * NBH + bh) * NT + t];
    ss = d_part_ss[(2 * NBH + bh) * NT + t] + d_part_ss[(3 * NBH + bh) * NT + t];
    m = s * (1.f / DQK); var = ss * (1.f / DQK) - m * m;
    d_muk[bh * NT + t] = m; d_rsk[bh * NT + t] = rsqrtf(var + EPSV);
    s = 0.f; ss = 0.f;
#pragma unroll
    for (int sl = 4; sl < 12; sl++) {
        s += d_part_s[(sl * NBH + bh) * NT + t];
        ss += d_part_ss[(sl * NBH + bh) * NT + t];
    }
    m = s * (1.f / DV); var = ss * (1.f / DV) - m * m;
    d_muv[bh * NT + t] = m; d_rsv[bh * NT + t] = rsqrtf(var + EPSV);
}

// ========== kernel 3a: scores + softmax -> coefficient vectors (SoA) ========
__global__ __launch_bounds__(128)
void k_score(const float* __restrict__ Kbuf,
             const float* __restrict__ gq, const float* __restrict__ beq,
             const float* __restrict__ gk, const float* __restrict__ bek)
{
    __shared__ float sp[32][4][4][12];

    const int tid = threadIdx.x;
    const int tl = tid & 3, dg = tid >> 2;
    const int bh = blockIdx.y;
    const int t0 = blockIdx.x * 16;
    const int t4 = t0 + 4 * tl;
    const int t4c = (t4 < NT) ? t4 : (NT - 4);

    const float* Qp = d_Qr + (size_t)bh * DQK * NT;
    const float* Kp = d_Kr + (size_t)bh * DQK * NT;

    {
        const float4 muq4 = *(const float4*)(d_muq + bh * NT + t4c);
        const float4 rsq4 = *(const float4*)(d_rsq + bh * NT + t4c);
        const float mu[4] = {muq4.x, muq4.y, muq4.z, muq4.w};
        const float rs[4] = {rsq4.x, rsq4.y, rsq4.z, rsq4.w};
        float s[4][10];
#pragma unroll
        for (int j = 0; j < 4; j++)
#pragma unroll
            for (int c = 0; c < 10; c++) s[j][c] = 0.f;
        float Qg[4] = {0.f, 0.f, 0.f, 0.f}, Qb[4] = {0.f, 0.f, 0.f, 0.f};

        int d0 = dg * 9, d1 = d0 + 9; if (d1 > DQK) d1 = DQK;
        for (int d = d0; d < d1; d++) {
            const float4 q4 = *(const float4*)(Qp + (size_t)d * NT + t4c);
            const float qv[4] = {q4.x, q4.y, q4.z, q4.w};
            const float gqd = gq[d], beqd = beq[d], gkd = gk[d], bekd = bek[d];
            float w[16];
            const float* kb = Kp + (size_t)d * NT + t4c - 12;
            *(float4*)&w[0]  = *(const float4*)(kb);
            *(float4*)&w[4]  = *(const float4*)(kb + 4);
            *(float4*)&w[8]  = *(const float4*)(kb + 8);
            *(float4*)&w[12] = *(const float4*)(kb + 12);
            float qg[4];
#pragma unroll
            for (int j = 0; j < 4; j++) {
                float qn = fmaf((qv[j] - mu[j]) * rs[j], gqd, beqd);
                qg[j] = qn * gkd;
                Qg[j] += qg[j];
                Qb[j] = fmaf(qn, bekd, Qb[j]);
            }
#pragma unroll
            for (int c = 0; c < 10; c++)
#pragma unroll
                for (int j = 0; j < 4; j++)
                    s[j][c] = fmaf(qg[j], w[3 + j + c], s[j][c]);
        }
#pragma unroll
        for (int j = 0; j < 4; j++) {
#pragma unroll
            for (int c = 0; c < 10; c++) sp[dg][tl][j][c] = s[j][c];
            sp[dg][tl][j][10] = Qg[j];
            sp[dg][tl][j][11] = Qb[j];
        }
    }
    __syncthreads();

    if (tid < 16) {
        const int tt = tid, jj = tt & 3, tln = tt >> 2;
        int t = t0 + tt;
        if (t >= NT) return;
        const int tc = t;
        float S[10], QG = 0.f, QB = 0.f;
#pragma unroll
        for (int c = 0; c < 10; c++) S[c] = 0.f;
#pragma unroll
        for (int g = 0; g < 32; g++) {
#pragma unroll
            for (int c = 0; c < 10; c++) S[c] += sp[g][tln][jj][c];
            QG += sp[g][tln][jj][10];
            QB += sp[g][tln][jj][11];
        }
        const int c0 = (tc < 9) ? (9 - tc) : 0;
#pragma unroll
        for (int c = 0; c < 10; c++) {
            int src = tc + c - 9;
            int sc = src < 0 ? 0 : src;
            float mk = d_muk[bh * NT + sc], rk = d_rsk[bh * NT + sc];
            S[c] = rk * (S[c] - mk * QG) + QB;
        }
        if (c0 > 0) {
            const float muq = d_muq[bh * NT + tc], rsq = d_rsq[bh * NT + tc];
            for (int c = 0; c < c0; c++) {
                const float* kb = Kbuf + ((size_t)bh * 9 + (tc + c)) * DQK;
                float acc = 0.f;
                for (int d = 0; d < DQK; d++) {
                    float qr = Qp[(size_t)d * NT + tc];
                    float qn = (qr - muq) * rsq * gq[d] + beq[d];
                    acc = fmaf(qn, kb[d], acc);
                }
                S[c] = acc;
            }
        }
        const float SCL = 0.0620173672946042252f;  // 1/sqrt(260)
        float mx = -1e30f;
#pragma unroll
        for (int c = 0; c < 10; c++) { S[c] *= SCL; mx = fmaxf(mx, S[c]); }
        float p[10], psum = 0.f;
#pragma unroll
        for (int c = 0; c < 10; c++) { p[c] = expf(S[c] - mx); psum += p[c]; }
        float inv = 1.f / psum;
        const int cfo = bh * NT + t;
        float boff = 0.f, P = 0.f;
#pragma unroll
        for (int c = 0; c < 10; c++) {
            p[c] *= inv;
            d_cf[c * CFSTR + cfo] = p[c];
            int src = tc + c - 9;
            float a = 0.f;
            if (src >= 0) {
                float mv_ = d_muv[bh * NT + src], rv_ = d_rsv[bh * NT + src];
                a = p[c] * rv_;
                boff -= a * mv_;
                P += p[c];
            }
            d_cf[(10 + c) * CFSTR + cfo] = a;
        }
        d_cf[20 * CFSTR + cfo] = boff;
        d_cf[21 * CFSTR + cfo] = P;
    }
}

// ========== kernel 3b: Vo FIR ===============================================
__global__ __launch_bounds__(256)
void k_vo(const float* __restrict__ Vbuf,
          const float* __restrict__ gv, const float* __restrict__ bev)
{
    const int tid = threadIdx.x;
    const int tl = tid & 31, dl = tid >> 5;
    const int bh = blockIdx.z;
    const int b = bh >> 3, h = bh & 7;
    const int t4 = blockIdx.x * 128 + 4 * tl;
    const bool vld = t4 < NT;
    const int t4c = vld ? t4 : (NT - 4);
    const int dbase = blockIdx.y * 80 + dl * 10;
    const int cfo = bh * NT + t4c;

    float a[4][10], boff[4], Pv[4];
#pragma unroll
    for (int c = 0; c < 10; c++) {
        float4 a4 = *(const float4*)(d_cf + (10 + c) * CFSTR + cfo);
        a[0][c] = a4.x; a[1][c] = a4.y; a[2][c] = a4.z; a[3][c] = a4.w;
    }
    {
        float4 b4 = *(const float4*)(d_cf + 20 * CFSTR + cfo);
        boff[0] = b4.x; boff[1] = b4.y; boff[2] = b4.z; boff[3] = b4.w;
        float4 p4 = *(const float4*)(d_cf + 21 * CFSTR + cfo);
        Pv[0] = p4.x; Pv[1] = p4.y; Pv[2] = p4.z; Pv[3] = p4.w;
    }
    const bool anybuf = (t4c < 9);
    const float* Vp = d_Vr + (size_t)bh * DV * NT;

#pragma unroll 2
    for (int i = 0; i < 10; i++) {
        const int d = dbase + i;
        float w[16];
        const float* vb = Vp + (size_t)d * NT + t4c - 12;
        *(float4*)&w[0]  = *(const float4*)(vb);
        *(float4*)&w[4]  = *(const float4*)(vb + 4);
        *(float4*)&w[8]  = *(const float4*)(vb + 8);
        *(float4*)&w[12] = *(const float4*)(vb + 12);
        float acc[4] = {boff[0], boff[1], boff[2], boff[3]};
#pragma unroll
        for (int c = 0; c < 10; c++)
#pragma unroll
            for (int j = 0; j < 4; j++)
                acc[j] = fmaf(a[j][c], w[3 + j + c], acc[j]);
        const float gvd = gv[d], bevd = bev[d];
        float vo[4];
#pragma unroll
        for (int j = 0; j < 4; j++) vo[j] = fmaf(gvd, acc[j], bevd * Pv[j]);
        if (anybuf) {
#pragma unroll
            for (int j = 0; j < 4; j++) {
                int tj = t4c + j;
                int cb = 9 - tj;
                for (int c = 0; c < cb; c++)
                    vo[j] = fmaf(d_cf[c * CFSTR + bh * NT + tj],
                                 Vbuf[((size_t)bh * 9 + (tj + c)) * DV + d], vo[j]);
            }
        }
        if (vld) {
            int f = d >> 4, dvv = d & 15;
            float4 o4 = make_float4(vo[0], vo[1], vo[2], vo[3]);
            *(float4*)(d_Z + (((size_t)b * NF + f) * NC + h * 16 + dvv) * NT + t4) = o4;
        }
    }
}

// ============ kernel 5: LN-P stats combine over 65 f-partials ===============
__global__ void k_statsP2() {
    int t = blockIdx.x * 128 + threadIdx.x;
    if (t >= NT) return;
    int b = blockIdx.y;
    float s = 0.f, ss = 0.f;
#pragma unroll 5
    for (int f = 0; f < NF; f++) {
        s += d_ps [(f * NB + b) * NT + t];
        ss += d_pss[(f * NB + b) * NT + t];
    }
    float m = s * (1.f / FC);
    float var = ss * (1.f / FC) - m * m;
    d_mup[b * NT + t] = m;
    d_rsp[b * NT + t] = rsqrtf(var + EPSV);
}

// ========== kernel 6: LN-P apply + residual + output (float4) ===============
__global__ void k_final(const float* __restrict__ x, const float* __restrict__ gp,
                        const float* __restrict__ bep, float* __restrict__ out)
{
    size_t idx4 = (size_t)blockIdx.x * 256 + threadIdx.x;
    if (idx4 >= (size_t)(OUT_ELEMS / 4)) return;
    size_t i = idx4 * 4;
    int t = (int)(i % NT);
    size_t r = i / NT;
    int f = (int)(r % NF); r /= NF;
    int o = (int)(r % NC);
    int b = (int)(r / NC);
    float4 y = *(const float4*)(d_Y + i);
    float4 xv = *(const float4*)(x + i);
    float4 m4 = *(const float4*)(d_mup + b * NT + t);
    float4 r4 = *(const float4*)(d_rsp + b * NT + t);
    int gi = f * NC + o;
    float g = gp[gi], be = bep[gi];
    float4 ov;
    ov.x = (y.x - m4.x) * r4.x * g + be + xv.x;
    ov.y = (y.y - m4.y) * r4.y * g + be + xv.y;
    ov.z = (y.z - m4.z) * r4.z * g + be + xv.z;
    ov.w = (y.w - m4.w) * r4.w * g + be + xv.w;
    *(float4*)(out + i) = ov;
}

// ================= kernel 7: K_buf_new / V_buf_new ==========================
__global__ void k_bufs(const float* __restrict__ gk, const float* __restrict__ bek,
                       const float* __restrict__ gv, const float* __restrict__ bev,
                       float* __restrict__ kout, float* __restrict__ vout)
{
    int idx = blockIdx.x * 256 + threadIdx.x;
    if (idx < KBUF_ELEMS) {
        int d = idx % DQK; int r = idx / DQK; int j = r % 9; int bh = r / 9;
        int t = 491 + j;
        float v = d_Kr[((size_t)bh * DQK + d) * NT + t];
        v = (v - d_muk[bh * NT + t]) * d_rsk[bh * NT + t] * gk[d] + bek[d];
        kout[idx] = v;
    } else {
        int i2 = idx - KBUF_ELEMS;
        if (i2 < VBUF_ELEMS) {
            int d = i2 % DV; int r = i2 / DV; int j = r % 9; int bh = r / 9;
            int t = 491 + j;
            float v = d_Vr[((size_t)bh * DV + d) * NT + t];
            v = (v - d_muv[bh * NT + t]) * d_rsv[bh * NT + t] * gv[d] + bev[d];
            vout[i2] = v;
        }
    }
}

// ================= launch ==================================================
extern "C" void kernel_launch(void* const* d_in, const int* in_sizes, int n_in,
                              void* d_out, int out_size)
{
    const float* x    = (const float*)d_in[0];
    const float* mc   = (const float*)d_in[1];
    const float* Kbuf = (const float*)d_in[2];
    const float* Vbuf = (const float*)d_in[3];
    const float* Wq   = (const float*)d_in[4];
    const float* bq   = (const float*)d_in[5];
    const float* aq   = (const float*)d_in[6];
    const float* gq   = (const float*)d_in[7];
    const float* beq  = (const float*)d_in[8];
    const float* Wk   = (const float*)d_in[9];
    const float* bk   = (const float*)d_in[10];
    const float* ak   = (const float*)d_in[11];
    const float* gk   = (const float*)d_in[12];
    const float* bek  = (const float*)d_in[13];
    const float* Wv   = (const float*)d_in[14];
    const float* bv   = (const float*)d_in[15];
    const float* av   = (const float*)d_in[16];
    const float* gv   = (const float*)d_in[17];
    const float* bev  = (const float*)d_in[18];
    const float* Wp   = (const float*)d_in[19];
    const float* bp   = (const float*)d_in[20];
    const float* ap   = (const float*)d_in[21];
    const float* gp   = (const float*)d_in[22];
    const float* bep  = (const float*)d_in[23];
    float* out = (float*)d_out;

    cudaFuncSetAttribute(k_kvq_mma, cudaFuncAttributeMaxDynamicSharedMemorySize, GEMM_SMEM);
    cudaFuncSetAttribute(k_p_mma,   cudaFuncAttributeMaxDynamicSharedMemorySize, GEMM_SMEM);

    // slots 0-2: warm + prep, so ncu's captured launch (index 3) = k_kvq_mma
    k_warm<<<8, 128>>>();
    k_warm<<<8, 128>>>();
    k_prep<<<160, 256>>>(Wq, Wk, Wv, Wp);
    k_kvq_mma<<<dim3(4, 65, 8), 256, GEMM_SMEM>>>(mc, x, bk, ak, bv, av, bq, aq);
    k_stats_part<<<dim3(4, 32, 12), 128>>>();
    k_stats_comb<<<dim3(4, 32), 128>>>();
    k_score<<<dim3(32, 32), 128>>>(Kbuf, gq, beq, gk, bek);
    k_vo<<<dim3(4, 13, 32), 256>>>(Vbuf, gv, bev);
    k_p_mma<<<dim3(4, 65, 4), 256, GEMM_SMEM>>>(bp, ap);
    k_statsP2<<<dim3(4, 4), 128>>>();
    k_final<<<(OUT_ELEMS / 4 + 255) / 256, 256>>>(x, gp, bep, out);
    k_bufs<<<(KBUF_ELEMS + VBUF_ELEMS + 255) / 256, 256>>>(gk, bek, gv, bev,
                                                           out + OUT_ELEMS,
                                                           out + OUT_ELEMS + KBUF_ELEMS);
}